// round 1
// baseline (speedup 1.0000x reference)
#include <cuda_runtime.h>
#include <cuda_bf16.h>

// Problem constants
#define BB 4
#define S1 2048
#define S2 2048
#define D1 512
#define D2 512
#define NH 8
#define DK 64
#define DV 64
#define MROWS (BB * S1)   // 8192
#define NCOLS (NH * DK)   // 512

// Scratch (device globals — no allocation allowed)
__device__ float g_Q[MROWS * NCOLS];
__device__ float g_K[MROWS * NCOLS];
__device__ float g_V[MROWS * NCOLS];
__device__ float g_ATT[MROWS * NCOLS];

// ---------------------------------------------------------------------------
// Tiled fp32 GEMM: C[M,N] = A[M,K] @ B[K,N] (+ bias[N] if bias != nullptr)
// BM=BN=64, BK=16, 256 threads, 4x4 micro-tile per thread.
// ---------------------------------------------------------------------------
#define BM 64
#define BN 64
#define BK 16

__global__ __launch_bounds__(256)
void gemm_kernel(const float* __restrict__ A, const float* __restrict__ B,
                 const float* __restrict__ bias, float* __restrict__ C,
                 int M, int N, int K)
{
    __shared__ float As[BK][BM];   // A tile stored transposed: As[k][m]
    __shared__ float Bs[BK][BN];

    const int tid = threadIdx.x;
    const int tx = tid & 15;        // 0..15
    const int ty = tid >> 4;        // 0..15
    const int row0 = blockIdx.y * BM;
    const int col0 = blockIdx.x * BN;

    // loader mapping
    const int a_row  = tid >> 2;          // 0..63
    const int a_k4   = (tid & 3) * 4;     // 0,4,8,12
    const int b_row  = tid >> 4;          // 0..15
    const int b_col4 = (tid & 15) * 4;    // 0..60

    float acc[4][4];
#pragma unroll
    for (int i = 0; i < 4; i++)
#pragma unroll
        for (int j = 0; j < 4; j++) acc[i][j] = 0.f;

    for (int k0 = 0; k0 < K; k0 += BK) {
        float4 av = *(const float4*)&A[(size_t)(row0 + a_row) * K + k0 + a_k4];
        As[a_k4 + 0][a_row] = av.x;
        As[a_k4 + 1][a_row] = av.y;
        As[a_k4 + 2][a_row] = av.z;
        As[a_k4 + 3][a_row] = av.w;
        *(float4*)&Bs[b_row][b_col4] =
            *(const float4*)&B[(size_t)(k0 + b_row) * N + col0 + b_col4];
        __syncthreads();

#pragma unroll
        for (int kk = 0; kk < BK; kk++) {
            float4 a4 = *(const float4*)&As[kk][ty * 4];
            float4 b4 = *(const float4*)&Bs[kk][tx * 4];
            float af[4] = {a4.x, a4.y, a4.z, a4.w};
            float bf[4] = {b4.x, b4.y, b4.z, b4.w};
#pragma unroll
            for (int i = 0; i < 4; i++)
#pragma unroll
                for (int j = 0; j < 4; j++)
                    acc[i][j] = fmaf(af[i], bf[j], acc[i][j]);
        }
        __syncthreads();
    }

#pragma unroll
    for (int i = 0; i < 4; i++) {
        const int r = row0 + ty * 4 + i;
        float4 o;
        o.x = acc[i][0]; o.y = acc[i][1]; o.z = acc[i][2]; o.w = acc[i][3];
        if (bias) {
            const float4 bz = *(const float4*)&bias[col0 + tx * 4];
            o.x += bz.x; o.y += bz.y; o.z += bz.z; o.w += bz.w;
        }
        *(float4*)&C[(size_t)r * N + col0 + tx * 4] = o;
    }
}

// ---------------------------------------------------------------------------
// Flash attention: one CTA = 64 queries of one (b,h).
// Q,K,V in [B*S, H*64] layout. Output written in [B, S1, H*DV] layout.
// smem: Qs (transposed, pre-scaled), Ks (transposed; reused to hold P), Vs.
// Static smem = 3 * 64*64*4 = 49152 B (exactly the 48KB static cap).
// ---------------------------------------------------------------------------
__global__ __launch_bounds__(256)
void attn_kernel(const float* __restrict__ Q, const float* __restrict__ K,
                 const float* __restrict__ V, float* __restrict__ O)
{
    __shared__ float Qs[64 * 64];   // Qs[d*64 + row]  (scaled by 1/8)
    __shared__ float Ks[64 * 64];   // Ks[d*64 + col]; later reused as P[row*64 + col]
    __shared__ float Vs[64 * 64];   // Vs[k*64 + d]

    const int tid = threadIdx.x;
    const int tx = tid & 15;
    const int ty = tid >> 4;
    const int tx4 = tx * 4;
    const int ty4 = ty * 4;

    const int bh = blockIdx.y;
    const int b = bh >> 3;          // / NH
    const int h = bh & 7;
    const int q0 = blockIdx.x * 64;

    const float* Qb = Q + (size_t)(b * S1 + q0) * NCOLS + h * DK;
    const float* Kb = K + (size_t)(b * S2) * NCOLS + h * DK;
    const float* Vb = V + (size_t)(b * S2) * NCOLS + h * DV;

    // load Q tile, transposed + pre-scaled by 1/sqrt(64) = 0.125
#pragma unroll
    for (int it = 0; it < 4; it++) {
        const int idx = tid + it * 256;      // 0..1023
        const int r  = idx >> 4;             // 0..63
        const int d4 = (idx & 15) * 4;       // 0..60
        float4 v = *(const float4*)&Qb[(size_t)r * NCOLS + d4];
        Qs[(d4 + 0) * 64 + r] = v.x * 0.125f;
        Qs[(d4 + 1) * 64 + r] = v.y * 0.125f;
        Qs[(d4 + 2) * 64 + r] = v.z * 0.125f;
        Qs[(d4 + 3) * 64 + r] = v.w * 0.125f;
    }

    float oacc[4][4];
    float m[4], l[4];
#pragma unroll
    for (int i = 0; i < 4; i++) {
        m[i] = -1e30f; l[i] = 0.f;
#pragma unroll
        for (int j = 0; j < 4; j++) oacc[i][j] = 0.f;
    }

    for (int kt = 0; kt < S2 / 64; kt++) {
        __syncthreads();   // protect Ks (P) / Vs from previous iteration
        // load K (transposed) and V (natural) tiles
#pragma unroll
        for (int it = 0; it < 4; it++) {
            const int idx = tid + it * 256;
            const int r  = idx >> 4;
            const int d4 = (idx & 15) * 4;
            float4 kv = *(const float4*)&Kb[(size_t)(kt * 64 + r) * NCOLS + d4];
            Ks[(d4 + 0) * 64 + r] = kv.x;
            Ks[(d4 + 1) * 64 + r] = kv.y;
            Ks[(d4 + 2) * 64 + r] = kv.z;
            Ks[(d4 + 3) * 64 + r] = kv.w;
            *(float4*)&Vs[r * 64 + d4] =
                *(const float4*)&Vb[(size_t)(kt * 64 + r) * NCOLS + d4];
        }
        __syncthreads();

        // S = Q @ K^T  (rows ty4+i, cols tx4+j)
        float s[4][4];
#pragma unroll
        for (int i = 0; i < 4; i++)
#pragma unroll
            for (int j = 0; j < 4; j++) s[i][j] = 0.f;

#pragma unroll 8
        for (int d = 0; d < 64; d++) {
            float4 a4 = *(const float4*)&Qs[d * 64 + ty4];
            float4 b4 = *(const float4*)&Ks[d * 64 + tx4];
            float af[4] = {a4.x, a4.y, a4.z, a4.w};
            float bf[4] = {b4.x, b4.y, b4.z, b4.w};
#pragma unroll
            for (int i = 0; i < 4; i++)
#pragma unroll
                for (int j = 0; j < 4; j++)
                    s[i][j] = fmaf(af[i], bf[j], s[i][j]);
        }

        // online softmax (row groups = 16 lanes sharing ty)
        float mnew[4], rs[4], alpha[4];
#pragma unroll
        for (int i = 0; i < 4; i++) {
            float mx = fmaxf(fmaxf(s[i][0], s[i][1]), fmaxf(s[i][2], s[i][3]));
#pragma unroll
            for (int off = 8; off > 0; off >>= 1)
                mx = fmaxf(mx, __shfl_xor_sync(0xffffffffu, mx, off, 16));
            mnew[i] = fmaxf(m[i], mx);
            alpha[i] = __expf(m[i] - mnew[i]);
            float sum = 0.f;
#pragma unroll
            for (int j = 0; j < 4; j++) {
                s[i][j] = __expf(s[i][j] - mnew[i]);
                sum += s[i][j];
            }
#pragma unroll
            for (int off = 8; off > 0; off >>= 1)
                sum += __shfl_xor_sync(0xffffffffu, sum, off, 16);
            rs[i] = sum;
        }
#pragma unroll
        for (int i = 0; i < 4; i++) {
            l[i] = l[i] * alpha[i] + rs[i];
            m[i] = mnew[i];
#pragma unroll
            for (int j = 0; j < 4; j++) oacc[i][j] *= alpha[i];
        }

        __syncthreads();   // everyone done reading Ks as K
        // store P into Ks buffer: P[row*64 + col]
#pragma unroll
        for (int i = 0; i < 4; i++) {
            float4 p4;
            p4.x = s[i][0]; p4.y = s[i][1]; p4.z = s[i][2]; p4.w = s[i][3];
            *(float4*)&Ks[(ty4 + i) * 64 + tx4] = p4;
        }
        __syncthreads();

        // O += P @ V
#pragma unroll 4
        for (int k4 = 0; k4 < 64; k4 += 4) {
            float4 pa[4];
#pragma unroll
            for (int i = 0; i < 4; i++)
                pa[i] = *(const float4*)&Ks[(ty4 + i) * 64 + k4];
#pragma unroll
            for (int kk = 0; kk < 4; kk++) {
                float4 vb = *(const float4*)&Vs[(k4 + kk) * 64 + tx4];
                float vf[4] = {vb.x, vb.y, vb.z, vb.w};
                float pf[4] = {pa[0].x, pa[1].x, pa[2].x, pa[3].x};
                if (kk == 1) { pf[0]=pa[0].y; pf[1]=pa[1].y; pf[2]=pa[2].y; pf[3]=pa[3].y; }
                if (kk == 2) { pf[0]=pa[0].z; pf[1]=pa[1].z; pf[2]=pa[2].z; pf[3]=pa[3].z; }
                if (kk == 3) { pf[0]=pa[0].w; pf[1]=pa[1].w; pf[2]=pa[2].w; pf[3]=pa[3].w; }
#pragma unroll
                for (int i = 0; i < 4; i++)
#pragma unroll
                    for (int j = 0; j < 4; j++)
                        oacc[i][j] = fmaf(pf[i], vf[j], oacc[i][j]);
            }
        }
    }

    // normalize and write out in [B, S1, H*DV] layout
#pragma unroll
    for (int i = 0; i < 4; i++) {
        const float rl = 1.0f / l[i];
        float4 o;
        o.x = oacc[i][0] * rl; o.y = oacc[i][1] * rl;
        o.z = oacc[i][2] * rl; o.w = oacc[i][3] * rl;
        const int row = b * S1 + q0 + ty4 + i;
        *(float4*)&O[(size_t)row * NCOLS + h * DV + tx4] = o;
    }
}

// ---------------------------------------------------------------------------
// Launch
// ---------------------------------------------------------------------------
extern "C" void kernel_launch(void* const* d_in, const int* in_sizes, int n_in,
                              void* d_out, int out_size)
{
    (void)in_sizes; (void)n_in; (void)out_size;
    const float* x1 = (const float*)d_in[0];
    const float* x2 = (const float*)d_in[1];
    const float* x3 = (const float*)d_in[2];
    const float* Wq = (const float*)d_in[3];
    const float* Wk = (const float*)d_in[4];
    const float* Wv = (const float*)d_in[5];
    const float* Wo = (const float*)d_in[6];
    const float* bo = (const float*)d_in[7];
    float* out = (float*)d_out;

    float *Q, *K, *V, *A;
    cudaGetSymbolAddress((void**)&Q, g_Q);
    cudaGetSymbolAddress((void**)&K, g_K);
    cudaGetSymbolAddress((void**)&V, g_V);
    cudaGetSymbolAddress((void**)&A, g_ATT);

    dim3 gGemm(NCOLS / BN, MROWS / BM);   // (8, 128)
    gemm_kernel<<<gGemm, 256>>>(x1, Wq, nullptr, Q, MROWS, NCOLS, D1);
    gemm_kernel<<<gGemm, 256>>>(x2, Wk, nullptr, K, MROWS, NCOLS, D2);
    gemm_kernel<<<gGemm, 256>>>(x3, Wv, nullptr, V, MROWS, NCOLS, D2);

    dim3 gAttn(S1 / 64, BB * NH);         // (32, 32)
    attn_kernel<<<gAttn, 256>>>(Q, K, V, A);

    gemm_kernel<<<gGemm, 256>>>(A, Wo, bo, out, MROWS, D1, NCOLS);
}

// round 4
// speedup vs baseline: 2.1122x; 2.1122x over previous
#include <cuda_runtime.h>
#include <cuda_bf16.h>
#include <cstdint>

// Problem constants
#define BB 4
#define S1C 2048
#define S2C 2048
#define NH 8
#define MROWS (BB * S1C)    // 8192
#define ND 512
#define KD 512

// Scratch (device globals — no allocation allowed)
__device__ float g_Q [MROWS * ND];
__device__ float g_K [MROWS * ND];
__device__ float g_V [MROWS * ND];
__device__ float g_ATT[MROWS * ND];
__device__ __nv_bfloat16 g_WTh[4 * (size_t)KD * ND];  // W^T [n][k] hi
__device__ __nv_bfloat16 g_WTl[4 * (size_t)KD * ND];  // W^T [n][k] lo residual

// ---------------------------------------------------------------------------
// helpers
// ---------------------------------------------------------------------------
__device__ __forceinline__ float to_tf32(float x) {
    float y;
    asm("cvt.rna.tf32.f32 %0, %1;" : "=f"(y) : "f"(x));
    return y;
}

// FFMA-only exp. Valid for |x| < ~80. rel err < 1e-7.
__device__ __forceinline__ float fast_exp(float x) {
    const float LOG2E = 1.4426950408889634f;
    float t = x * LOG2E;
    float r = t + 12582912.0f;
    float n = r - 12582912.0f;
    float f = t - n;
    int   ni = __float_as_int(r) - 0x4B400000;
    float p = 0.0013333558f;
    p = fmaf(p, f, 0.0096181291f);
    p = fmaf(p, f, 0.0555041087f);
    p = fmaf(p, f, 0.2402265070f);
    p = fmaf(p, f, 0.6931471806f);
    p = fmaf(p, f, 1.0f);
    return __int_as_float(__float_as_int(p) + (ni << 23));
}

// D += A(16x16 bf16) @ B(16x8 bf16 col-major)
__device__ __forceinline__ void mma_bf16(float* c, const uint32_t* a, const uint32_t* b) {
    asm volatile(
        "mma.sync.aligned.m16n8k16.row.col.f32.bf16.bf16.f32 "
        "{%0,%1,%2,%3}, {%4,%5,%6,%7}, {%8,%9}, {%0,%1,%2,%3};"
        : "+f"(c[0]), "+f"(c[1]), "+f"(c[2]), "+f"(c[3])
        : "r"(a[0]), "r"(a[1]), "r"(a[2]), "r"(a[3]), "r"(b[0]), "r"(b[1]));
}

// D += A(16x8 tf32) @ B(8x8 tf32 col-major)
__device__ __forceinline__ void mma_tf32(float* c, const uint32_t* a, const uint32_t* b) {
    asm volatile(
        "mma.sync.aligned.m16n8k8.row.col.f32.tf32.tf32.f32 "
        "{%0,%1,%2,%3}, {%4,%5,%6,%7}, {%8,%9}, {%0,%1,%2,%3};"
        : "+f"(c[0]), "+f"(c[1]), "+f"(c[2]), "+f"(c[3])
        : "r"(a[0]), "r"(a[1]), "r"(a[2]), "r"(a[3]), "r"(b[0]), "r"(b[1]));
}

__device__ __forceinline__ uint32_t pack2(__nv_bfloat16 a, __nv_bfloat16 b) {
    return (uint32_t)__bfloat16_as_ushort(a) | ((uint32_t)__bfloat16_as_ushort(b) << 16);
}

// ---------------------------------------------------------------------------
// prep: W[k][n] (512x512 fp32) -> g_WTh/g_WTl [n][k] bf16 hi/lo
// grid (16,16,4), 256 threads
// ---------------------------------------------------------------------------
__global__ __launch_bounds__(256)
void prep_w(const float* __restrict__ Wq, const float* __restrict__ Wk,
            const float* __restrict__ Wv, const float* __restrict__ Wo)
{
    __shared__ float tbuf[32][33];
    const int z = blockIdx.z;
    const float* W = (z == 0) ? Wq : (z == 1) ? Wk : (z == 2) ? Wv : Wo;
    __nv_bfloat16* oh = g_WTh + (size_t)z * KD * ND;
    __nv_bfloat16* ol = g_WTl + (size_t)z * KD * ND;
    const int k0 = blockIdx.x * 32, n0 = blockIdx.y * 32;
    const int lane = threadIdx.x & 31, r = threadIdx.x >> 5;

#pragma unroll
    for (int i = 0; i < 4; i++) {
        const int row = r + i * 8;
        tbuf[row][lane] = W[(size_t)(k0 + row) * ND + n0 + lane];
    }
    __syncthreads();
#pragma unroll
    for (int i = 0; i < 4; i++) {
        const int row = r + i * 8;              // n index within tile
        const float x = tbuf[lane][row];        // W[k0+lane][n0+row]
        const __nv_bfloat16 hb = __float2bfloat16(x);
        oh[(size_t)(n0 + row) * KD + k0 + lane] = hb;
        ol[(size_t)(n0 + row) * KD + k0 + lane] =
            __float2bfloat16(x - __bfloat162float(hb));
    }
}

// ---------------------------------------------------------------------------
// bf16x3 tensor-core GEMM: C[8192,512] = A[8192,512] @ W[512,512] (+bias)
// CTA 128x128, 8 warps (2m x 4n), warp 64x32, BK=32, reg-prefetch pipelined.
// ---------------------------------------------------------------------------
#define ASTR 40   // bf16 per smem row (32 + 8 pad)

__global__ __launch_bounds__(256)
void gemm_mma(const float* __restrict__ A, const __nv_bfloat16* __restrict__ Bh,
              const __nv_bfloat16* __restrict__ Bl, const float* __restrict__ bias,
              float* __restrict__ C)
{
    __shared__ __nv_bfloat16 Ah[128 * ASTR], Al[128 * ASTR];
    __shared__ __nv_bfloat16 Bsh[128 * ASTR], Bsl[128 * ASTR];

    const int tid = threadIdx.x;
    const int lane = tid & 31;
    const int w = tid >> 5;
    const int wm = w & 1, wn = w >> 1;
    const int r = lane >> 2, cq = lane & 3;
    const int m0 = blockIdx.y * 128, n0 = blockIdx.x * 128;

    float c[4][4][4];
#pragma unroll
    for (int i = 0; i < 4; i++)
#pragma unroll
        for (int j = 0; j < 4; j++)
#pragma unroll
            for (int x = 0; x < 4; x++) c[i][j][x] = 0.f;

    float4 av[4];
    uint4 bvh[2], bvl[2];

    // prefetch k-tile 0
#pragma unroll
    for (int it = 0; it < 4; it++) {
        const int q = tid + it * 256;
        av[it] = *(const float4*)&A[(size_t)(m0 + (q >> 3)) * KD + (q & 7) * 4];
    }
#pragma unroll
    for (int it = 0; it < 2; it++) {
        const int q = tid + it * 256;
        bvh[it] = *(const uint4*)&Bh[(size_t)(n0 + (q >> 2)) * KD + (q & 3) * 8];
        bvl[it] = *(const uint4*)&Bl[(size_t)(n0 + (q >> 2)) * KD + (q & 3) * 8];
    }

    for (int kt = 0; kt < 16; kt++) {
        __syncthreads();
        // store A hi/lo split
#pragma unroll
        for (int it = 0; it < 4; it++) {
            const int q = tid + it * 256;
            const int row = q >> 3, kq = (q & 7) * 4;
            const float4 v = av[it];
            __nv_bfloat16 h0 = __float2bfloat16(v.x), h1 = __float2bfloat16(v.y),
                          h2 = __float2bfloat16(v.z), h3 = __float2bfloat16(v.w);
            uint2 ph = make_uint2(pack2(h0, h1), pack2(h2, h3));
            uint2 pl = make_uint2(
                pack2(__float2bfloat16(v.x - __bfloat162float(h0)),
                      __float2bfloat16(v.y - __bfloat162float(h1))),
                pack2(__float2bfloat16(v.z - __bfloat162float(h2)),
                      __float2bfloat16(v.w - __bfloat162float(h3))));
            *(uint2*)&Ah[row * ASTR + kq] = ph;
            *(uint2*)&Al[row * ASTR + kq] = pl;
        }
#pragma unroll
        for (int it = 0; it < 2; it++) {
            const int q = tid + it * 256;
            const int row = q >> 2, seg = (q & 3) * 8;
            *(uint4*)&Bsh[row * ASTR + seg] = bvh[it];
            *(uint4*)&Bsl[row * ASTR + seg] = bvl[it];
        }
        __syncthreads();

        // prefetch next k-tile
        if (kt < 15) {
            const int k0 = (kt + 1) * 32;
#pragma unroll
            for (int it = 0; it < 4; it++) {
                const int q = tid + it * 256;
                av[it] = *(const float4*)&A[(size_t)(m0 + (q >> 3)) * KD + k0 + (q & 7) * 4];
            }
#pragma unroll
            for (int it = 0; it < 2; it++) {
                const int q = tid + it * 256;
                bvh[it] = *(const uint4*)&Bh[(size_t)(n0 + (q >> 2)) * KD + k0 + (q & 3) * 8];
                bvl[it] = *(const uint4*)&Bl[(size_t)(n0 + (q >> 2)) * KD + k0 + (q & 3) * 8];
            }
        }

        // compute 2 k16 steps
#pragma unroll
        for (int ks = 0; ks < 2; ks++) {
            const int kb = ks * 16 + 2 * cq;
            uint32_t ah[4][4], al4[4][4];
#pragma unroll
            for (int i = 0; i < 4; i++) {
                const int row = wm * 64 + i * 16 + r;
                ah[i][0] = *(const uint32_t*)&Ah[row * ASTR + kb];
                ah[i][1] = *(const uint32_t*)&Ah[(row + 8) * ASTR + kb];
                ah[i][2] = *(const uint32_t*)&Ah[row * ASTR + kb + 8];
                ah[i][3] = *(const uint32_t*)&Ah[(row + 8) * ASTR + kb + 8];
                al4[i][0] = *(const uint32_t*)&Al[row * ASTR + kb];
                al4[i][1] = *(const uint32_t*)&Al[(row + 8) * ASTR + kb];
                al4[i][2] = *(const uint32_t*)&Al[row * ASTR + kb + 8];
                al4[i][3] = *(const uint32_t*)&Al[(row + 8) * ASTR + kb + 8];
            }
#pragma unroll
            for (int j = 0; j < 4; j++) {
                const int n = wn * 32 + j * 8 + r;
                uint32_t bh2[2] = { *(const uint32_t*)&Bsh[n * ASTR + kb],
                                    *(const uint32_t*)&Bsh[n * ASTR + kb + 8] };
                uint32_t bl2[2] = { *(const uint32_t*)&Bsl[n * ASTR + kb],
                                    *(const uint32_t*)&Bsl[n * ASTR + kb + 8] };
#pragma unroll
                for (int i = 0; i < 4; i++) {
                    mma_bf16(c[i][j], ah[i], bh2);
                    mma_bf16(c[i][j], ah[i], bl2);
                    mma_bf16(c[i][j], al4[i], bh2);
                }
            }
        }
    }

    // epilogue
#pragma unroll
    for (int i = 0; i < 4; i++) {
        const int row = m0 + wm * 64 + i * 16 + r;
#pragma unroll
        for (int j = 0; j < 4; j++) {
            const int col = n0 + wn * 32 + j * 8 + 2 * cq;
            float2 v0 = make_float2(c[i][j][0], c[i][j][1]);
            float2 v1 = make_float2(c[i][j][2], c[i][j][3]);
            if (bias) {
                const float2 bz = *(const float2*)&bias[col];
                v0.x += bz.x; v0.y += bz.y;
                v1.x += bz.x; v1.y += bz.y;
            }
            *(float2*)&C[(size_t)row * ND + col] = v0;
            *(float2*)&C[(size_t)(row + 8) * ND + col] = v1;
        }
    }
}

// ---------------------------------------------------------------------------
// Flash attention, tf32 mma. CTA = 128 queries x one (b,h), 8 warps.
// KV tiles of 64. Unshifted softmax -> O is a pure accumulator.
// ---------------------------------------------------------------------------
#define QSTR 68
#define VSTR 65
#define SM_QS 0
#define SM_KS (128 * QSTR)                    // 8704
#define SM_VT (SM_KS + 64 * QSTR)             // +4352
#define SM_PS (SM_VT + 64 * VSTR)             // +4160
#define SM_ATT_FLOATS (SM_PS + 128 * QSTR)    // 25920 floats = 103680 B

__global__ __launch_bounds__(256, 2)
void attn_mma(const float* __restrict__ Q, const float* __restrict__ K,
              const float* __restrict__ V, float* __restrict__ O)
{
    extern __shared__ float sm[];
    float* Qs = sm + SM_QS;
    float* Ks = sm + SM_KS;
    float* Vt = sm + SM_VT;
    float* Ps = sm + SM_PS;

    const int tid = threadIdx.x;
    const int lane = tid & 31;
    const int wq = tid >> 5;          // warp -> 16 query rows
    const int r = lane >> 2, cq = lane & 3;

    const int bh = blockIdx.y;
    const int b = bh >> 3, h = bh & 7;
    const int q0 = blockIdx.x * 128;

    const float* Qb = Q + (size_t)(b * S1C + q0) * ND + h * 64;
    const float* Kb = K + (size_t)(b * S2C) * ND + h * 64;
    const float* Vb = V + (size_t)(b * S2C) * ND + h * 64;

    // stage Q (scaled by 1/8, tf32)
#pragma unroll
    for (int it = 0; it < 8; it++) {
        const int q = tid + it * 256;
        const int row = q >> 4, d4 = (q & 15) * 4;
        float4 v = *(const float4*)&Qb[(size_t)row * ND + d4];
        float* dst = &Qs[row * QSTR + d4];
        dst[0] = to_tf32(v.x * 0.125f);
        dst[1] = to_tf32(v.y * 0.125f);
        dst[2] = to_tf32(v.z * 0.125f);
        dst[3] = to_tf32(v.w * 0.125f);
    }

    float o[8][4];
#pragma unroll
    for (int j = 0; j < 8; j++)
#pragma unroll
        for (int x = 0; x < 4; x++) o[j][x] = 0.f;
    float l0 = 0.f, l1 = 0.f;

    const int prow0 = wq * 16 + r;

    for (int kt = 0; kt < S2C / 64; kt++) {
        __syncthreads();
        // load K (tf32) and V (tf32, transposed)
#pragma unroll
        for (int it = 0; it < 4; it++) {
            const int q = tid + it * 256;
            const int row = q >> 4, d4 = (q & 15) * 4;
            float4 kv = *(const float4*)&Kb[(size_t)(kt * 64 + row) * ND + d4];
            float* kd = &Ks[row * QSTR + d4];
            kd[0] = to_tf32(kv.x); kd[1] = to_tf32(kv.y);
            kd[2] = to_tf32(kv.z); kd[3] = to_tf32(kv.w);
            float4 vv = *(const float4*)&Vb[(size_t)(kt * 64 + row) * ND + d4];
            Vt[(d4 + 0) * VSTR + row] = to_tf32(vv.x);
            Vt[(d4 + 1) * VSTR + row] = to_tf32(vv.y);
            Vt[(d4 + 2) * VSTR + row] = to_tf32(vv.z);
            Vt[(d4 + 3) * VSTR + row] = to_tf32(vv.w);
        }
        __syncthreads();

        // S = Q @ K^T
        float s8[8][4];
#pragma unroll
        for (int j = 0; j < 8; j++)
#pragma unroll
            for (int x = 0; x < 4; x++) s8[j][x] = 0.f;

#pragma unroll
        for (int kf = 0; kf < 8; kf++) {
            const int kc = kf * 8 + cq;
            uint32_t qa[4];
            qa[0] = *(const uint32_t*)&Qs[prow0 * QSTR + kc];
            qa[1] = *(const uint32_t*)&Qs[(prow0 + 8) * QSTR + kc];
            qa[2] = *(const uint32_t*)&Qs[prow0 * QSTR + kc + 4];
            qa[3] = *(const uint32_t*)&Qs[(prow0 + 8) * QSTR + kc + 4];
#pragma unroll
            for (int j = 0; j < 8; j++) {
                uint32_t kb2[2];
                kb2[0] = *(const uint32_t*)&Ks[(j * 8 + r) * QSTR + kc];
                kb2[1] = *(const uint32_t*)&Ks[(j * 8 + r) * QSTR + kc + 4];
                mma_tf32(s8[j], qa, kb2);
            }
        }

        // unshifted softmax partial sums
        float sum0 = 0.f, sum1 = 0.f;
#pragma unroll
        for (int j = 0; j < 8; j++) {
            s8[j][0] = fast_exp(s8[j][0]);
            s8[j][1] = fast_exp(s8[j][1]);
            s8[j][2] = fast_exp(s8[j][2]);
            s8[j][3] = fast_exp(s8[j][3]);
            sum0 += s8[j][0] + s8[j][1];
            sum1 += s8[j][2] + s8[j][3];
        }
        sum0 += __shfl_xor_sync(0xffffffffu, sum0, 1);
        sum0 += __shfl_xor_sync(0xffffffffu, sum0, 2);
        sum1 += __shfl_xor_sync(0xffffffffu, sum1, 1);
        sum1 += __shfl_xor_sync(0xffffffffu, sum1, 2);
        l0 += sum0; l1 += sum1;

        // P -> smem (tf32)
        __syncwarp();
#pragma unroll
        for (int j = 0; j < 8; j++) {
            const int col = j * 8 + 2 * cq;
            float* p0 = &Ps[prow0 * QSTR + col];
            p0[0] = to_tf32(s8[j][0]); p0[1] = to_tf32(s8[j][1]);
            float* p1 = &Ps[(prow0 + 8) * QSTR + col];
            p1[0] = to_tf32(s8[j][2]); p1[1] = to_tf32(s8[j][3]);
        }
        __syncwarp();

        // O += P @ V
#pragma unroll
        for (int kf = 0; kf < 8; kf++) {
            const int kc = kf * 8 + cq;
            uint32_t pa[4];
            pa[0] = *(const uint32_t*)&Ps[prow0 * QSTR + kc];
            pa[1] = *(const uint32_t*)&Ps[(prow0 + 8) * QSTR + kc];
            pa[2] = *(const uint32_t*)&Ps[prow0 * QSTR + kc + 4];
            pa[3] = *(const uint32_t*)&Ps[(prow0 + 8) * QSTR + kc + 4];
#pragma unroll
            for (int j = 0; j < 8; j++) {
                uint32_t vb2[2];
                vb2[0] = *(const uint32_t*)&Vt[(j * 8 + r) * VSTR + kc];
                vb2[1] = *(const uint32_t*)&Vt[(j * 8 + r) * VSTR + kc + 4];
                mma_tf32(o[j], pa, vb2);
            }
        }
    }

    // normalize + write [B, S1, H*DV]
    const float rl0 = 1.0f / l0, rl1 = 1.0f / l1;
    const int grow = b * S1C + q0 + wq * 16 + r;
#pragma unroll
    for (int j = 0; j < 8; j++) {
        const int col = h * 64 + j * 8 + 2 * cq;
        float2 v0 = make_float2(o[j][0] * rl0, o[j][1] * rl0);
        float2 v1 = make_float2(o[j][2] * rl1, o[j][3] * rl1);
        *(float2*)&O[(size_t)grow * ND + col] = v0;
        *(float2*)&O[(size_t)(grow + 8) * ND + col] = v1;
    }
}

// ---------------------------------------------------------------------------
// Launch
// ---------------------------------------------------------------------------
extern "C" void kernel_launch(void* const* d_in, const int* in_sizes, int n_in,
                              void* d_out, int out_size)
{
    (void)in_sizes; (void)n_in; (void)out_size;
    const float* x1 = (const float*)d_in[0];
    const float* x2 = (const float*)d_in[1];
    const float* x3 = (const float*)d_in[2];
    const float* Wq = (const float*)d_in[3];
    const float* Wk = (const float*)d_in[4];
    const float* Wv = (const float*)d_in[5];
    const float* Wo = (const float*)d_in[6];
    const float* bo = (const float*)d_in[7];
    float* out = (float*)d_out;

    float *Q, *K, *V, *A;
    cudaGetSymbolAddress((void**)&Q, g_Q);
    cudaGetSymbolAddress((void**)&K, g_K);
    cudaGetSymbolAddress((void**)&V, g_V);
    cudaGetSymbolAddress((void**)&A, g_ATT);
    __nv_bfloat16 *WTh, *WTl;
    cudaGetSymbolAddress((void**)&WTh, g_WTh);
    cudaGetSymbolAddress((void**)&WTl, g_WTl);

    static int attr_done = 0;
    if (!attr_done) {
        cudaFuncSetAttribute(attn_mma, cudaFuncAttributeMaxDynamicSharedMemorySize,
                             SM_ATT_FLOATS * 4 + 256);
        attr_done = 1;
    }

    // weight prep (idempotent, deterministic)
    prep_w<<<dim3(16, 16, 4), 256>>>(Wq, Wk, Wv, Wo);

    const size_t WSZ = (size_t)KD * ND;
    dim3 gG(ND / 128, MROWS / 128);   // (4, 64)
    gemm_mma<<<gG, 256>>>(x1, WTh + 0 * WSZ, WTl + 0 * WSZ, nullptr, Q);
    gemm_mma<<<gG, 256>>>(x2, WTh + 1 * WSZ, WTl + 1 * WSZ, nullptr, K);
    gemm_mma<<<gG, 256>>>(x3, WTh + 2 * WSZ, WTl + 2 * WSZ, nullptr, V);

    dim3 gA(S1C / 128, BB * NH);      // (16, 32)
    attn_mma<<<gA, 256, SM_ATT_FLOATS * 4 + 256>>>(Q, K, V, A);

    gemm_mma<<<gG, 256>>>(A, WTh + 3 * WSZ, WTl + 3 * WSZ, bo, out);
}

// round 7
// speedup vs baseline: 2.8387x; 1.3439x over previous
#include <cuda_runtime.h>
#include <cuda_bf16.h>
#include <cstdint>

// Problem constants
#define BB 4
#define S1C 2048
#define S2C 2048
#define NH 8
#define MROWS (BB * S1C)    // 8192
#define ND 512
#define KD 512

// Scratch (device globals — no allocation allowed)
__device__ float g_Q [MROWS * ND];
__device__ float g_K [MROWS * ND];
__device__ float g_V [MROWS * ND];
__device__ float g_ATT[MROWS * ND];
__device__ __nv_bfloat16 g_WTh[4 * (size_t)KD * ND];  // W^T [n][k] hi
__device__ __nv_bfloat16 g_WTl[4 * (size_t)KD * ND];  // W^T [n][k] lo residual

// ---------------------------------------------------------------------------
// helpers
// ---------------------------------------------------------------------------
__device__ __forceinline__ uint32_t smem_u32(const void* p) {
    uint32_t a;
    asm("{ .reg .u64 t; cvta.to.shared.u64 t, %1; cvt.u32.u64 %0, t; }"
        : "=r"(a) : "l"(p));
    return a;
}

__device__ __forceinline__ void cp16(uint32_t dst, const void* src) {
    asm volatile("cp.async.cg.shared.global [%0], [%1], 16;"
                 :: "r"(dst), "l"(src) : "memory");
}
#define CP_COMMIT() asm volatile("cp.async.commit_group;" ::: "memory")
#define CP_WAIT0()  asm volatile("cp.async.wait_group 0;" ::: "memory")

__device__ __forceinline__ float to_tf32(float x) {
    float y;
    asm("cvt.rna.tf32.f32 %0, %1;" : "=f"(y) : "f"(x));
    return y;
}

// FFMA-only exp. Valid for |x| < ~80. rel err < 1e-7.
__device__ __forceinline__ float fast_exp(float x) {
    const float LOG2E = 1.4426950408889634f;
    float t = x * LOG2E;
    float r = t + 12582912.0f;
    float n = r - 12582912.0f;
    float f = t - n;
    int   ni = __float_as_int(r) - 0x4B400000;
    float p = 0.0013333558f;
    p = fmaf(p, f, 0.0096181291f);
    p = fmaf(p, f, 0.0555041087f);
    p = fmaf(p, f, 0.2402265070f);
    p = fmaf(p, f, 0.6931471806f);
    p = fmaf(p, f, 1.0f);
    return __int_as_float(__float_as_int(p) + (ni << 23));
}

__device__ __forceinline__ void mma_bf16(float* c, const uint32_t* a, const uint32_t* b) {
    asm volatile(
        "mma.sync.aligned.m16n8k16.row.col.f32.bf16.bf16.f32 "
        "{%0,%1,%2,%3}, {%4,%5,%6,%7}, {%8,%9}, {%0,%1,%2,%3};"
        : "+f"(c[0]), "+f"(c[1]), "+f"(c[2]), "+f"(c[3])
        : "r"(a[0]), "r"(a[1]), "r"(a[2]), "r"(a[3]), "r"(b[0]), "r"(b[1]));
}

__device__ __forceinline__ void mma_tf32(float* c, const uint32_t* a, const uint32_t* b) {
    asm volatile(
        "mma.sync.aligned.m16n8k8.row.col.f32.tf32.tf32.f32 "
        "{%0,%1,%2,%3}, {%4,%5,%6,%7}, {%8,%9}, {%0,%1,%2,%3};"
        : "+f"(c[0]), "+f"(c[1]), "+f"(c[2]), "+f"(c[3])
        : "r"(a[0]), "r"(a[1]), "r"(a[2]), "r"(a[3]), "r"(b[0]), "r"(b[1]));
}

__device__ __forceinline__ uint32_t pack2(__nv_bfloat16 a, __nv_bfloat16 b) {
    return (uint32_t)__bfloat16_as_ushort(a) | ((uint32_t)__bfloat16_as_ushort(b) << 16);
}

// ---------------------------------------------------------------------------
// prep: W[k][n] (512x512 fp32) -> g_WTh/g_WTl [n][k] bf16 hi/lo
// ---------------------------------------------------------------------------
__global__ __launch_bounds__(256)
void prep_w(const float* __restrict__ Wq, const float* __restrict__ Wk,
            const float* __restrict__ Wv, const float* __restrict__ Wo)
{
    __shared__ float tbuf[32][33];
    const int z = blockIdx.z;
    const float* W = (z == 0) ? Wq : (z == 1) ? Wk : (z == 2) ? Wv : Wo;
    __nv_bfloat16* oh = g_WTh + (size_t)z * KD * ND;
    __nv_bfloat16* ol = g_WTl + (size_t)z * KD * ND;
    const int k0 = blockIdx.x * 32, n0 = blockIdx.y * 32;
    const int lane = threadIdx.x & 31, r = threadIdx.x >> 5;

#pragma unroll
    for (int i = 0; i < 4; i++) {
        const int row = r + i * 8;
        tbuf[row][lane] = W[(size_t)(k0 + row) * ND + n0 + lane];
    }
    __syncthreads();
#pragma unroll
    for (int i = 0; i < 4; i++) {
        const int row = r + i * 8;
        const float x = tbuf[lane][row];
        const __nv_bfloat16 hb = __float2bfloat16(x);
        oh[(size_t)(n0 + row) * KD + k0 + lane] = hb;
        ol[(size_t)(n0 + row) * KD + k0 + lane] =
            __float2bfloat16(x - __bfloat162float(hb));
    }
}

// ---------------------------------------------------------------------------
// bf16x3 tensor-core GEMM (EXACT copy of the R4 passing kernel).
// C[8192,512] = A[8192,512] @ W[512,512] (+bias). CTA 128x128, 8 warps.
// ---------------------------------------------------------------------------
#define ASTR 40   // bf16 per smem row (32 + 8 pad)

__global__ __launch_bounds__(256)
void gemm_mma(const float* __restrict__ A, const __nv_bfloat16* __restrict__ Bh,
              const __nv_bfloat16* __restrict__ Bl, const float* __restrict__ bias,
              float* __restrict__ C)
{
    __shared__ __nv_bfloat16 Ah[128 * ASTR], Al[128 * ASTR];
    __shared__ __nv_bfloat16 Bsh[128 * ASTR], Bsl[128 * ASTR];

    const int tid = threadIdx.x;
    const int lane = tid & 31;
    const int w = tid >> 5;
    const int wm = w & 1, wn = w >> 1;
    const int r = lane >> 2, cq = lane & 3;
    const int m0 = blockIdx.y * 128, n0 = blockIdx.x * 128;

    float c[4][4][4];
#pragma unroll
    for (int i = 0; i < 4; i++)
#pragma unroll
        for (int j = 0; j < 4; j++)
#pragma unroll
            for (int x = 0; x < 4; x++) c[i][j][x] = 0.f;

    float4 av[4];
    uint4 bvh[2], bvl[2];

    // prefetch k-tile 0
#pragma unroll
    for (int it = 0; it < 4; it++) {
        const int q = tid + it * 256;
        av[it] = *(const float4*)&A[(size_t)(m0 + (q >> 3)) * KD + (q & 7) * 4];
    }
#pragma unroll
    for (int it = 0; it < 2; it++) {
        const int q = tid + it * 256;
        bvh[it] = *(const uint4*)&Bh[(size_t)(n0 + (q >> 2)) * KD + (q & 3) * 8];
        bvl[it] = *(const uint4*)&Bl[(size_t)(n0 + (q >> 2)) * KD + (q & 3) * 8];
    }

    for (int kt = 0; kt < 16; kt++) {
        __syncthreads();
#pragma unroll
        for (int it = 0; it < 4; it++) {
            const int q = tid + it * 256;
            const int row = q >> 3, kq = (q & 7) * 4;
            const float4 v = av[it];
            __nv_bfloat16 h0 = __float2bfloat16(v.x), h1 = __float2bfloat16(v.y),
                          h2 = __float2bfloat16(v.z), h3 = __float2bfloat16(v.w);
            uint2 ph = make_uint2(pack2(h0, h1), pack2(h2, h3));
            uint2 pl = make_uint2(
                pack2(__float2bfloat16(v.x - __bfloat162float(h0)),
                      __float2bfloat16(v.y - __bfloat162float(h1))),
                pack2(__float2bfloat16(v.z - __bfloat162float(h2)),
                      __float2bfloat16(v.w - __bfloat162float(h3))));
            *(uint2*)&Ah[row * ASTR + kq] = ph;
            *(uint2*)&Al[row * ASTR + kq] = pl;
        }
#pragma unroll
        for (int it = 0; it < 2; it++) {
            const int q = tid + it * 256;
            const int row = q >> 2, seg = (q & 3) * 8;
            *(uint4*)&Bsh[row * ASTR + seg] = bvh[it];
            *(uint4*)&Bsl[row * ASTR + seg] = bvl[it];
        }
        __syncthreads();

        if (kt < 15) {
            const int k0 = (kt + 1) * 32;
#pragma unroll
            for (int it = 0; it < 4; it++) {
                const int q = tid + it * 256;
                av[it] = *(const float4*)&A[(size_t)(m0 + (q >> 3)) * KD + k0 + (q & 7) * 4];
            }
#pragma unroll
            for (int it = 0; it < 2; it++) {
                const int q = tid + it * 256;
                bvh[it] = *(const uint4*)&Bh[(size_t)(n0 + (q >> 2)) * KD + k0 + (q & 3) * 8];
                bvl[it] = *(const uint4*)&Bl[(size_t)(n0 + (q >> 2)) * KD + k0 + (q & 3) * 8];
            }
        }

#pragma unroll
        for (int ks = 0; ks < 2; ks++) {
            const int kb = ks * 16 + 2 * cq;
            uint32_t ah[4][4], al4[4][4];
#pragma unroll
            for (int i = 0; i < 4; i++) {
                const int row = wm * 64 + i * 16 + r;
                ah[i][0] = *(const uint32_t*)&Ah[row * ASTR + kb];
                ah[i][1] = *(const uint32_t*)&Ah[(row + 8) * ASTR + kb];
                ah[i][2] = *(const uint32_t*)&Ah[row * ASTR + kb + 8];
                ah[i][3] = *(const uint32_t*)&Ah[(row + 8) * ASTR + kb + 8];
                al4[i][0] = *(const uint32_t*)&Al[row * ASTR + kb];
                al4[i][1] = *(const uint32_t*)&Al[(row + 8) * ASTR + kb];
                al4[i][2] = *(const uint32_t*)&Al[row * ASTR + kb + 8];
                al4[i][3] = *(const uint32_t*)&Al[(row + 8) * ASTR + kb + 8];
            }
#pragma unroll
            for (int j = 0; j < 4; j++) {
                const int n = wn * 32 + j * 8 + r;
                uint32_t bh2[2] = { *(const uint32_t*)&Bsh[n * ASTR + kb],
                                    *(const uint32_t*)&Bsh[n * ASTR + kb + 8] };
                uint32_t bl2[2] = { *(const uint32_t*)&Bsl[n * ASTR + kb],
                                    *(const uint32_t*)&Bsl[n * ASTR + kb + 8] };
#pragma unroll
                for (int i = 0; i < 4; i++) {
                    mma_bf16(c[i][j], ah[i], bh2);
                    mma_bf16(c[i][j], ah[i], bl2);
                    mma_bf16(c[i][j], al4[i], bh2);
                }
            }
        }
    }

#pragma unroll
    for (int i = 0; i < 4; i++) {
        const int row = m0 + wm * 64 + i * 16 + r;
#pragma unroll
        for (int j = 0; j < 4; j++) {
            const int col = n0 + wn * 32 + j * 8 + 2 * cq;
            float2 v0 = make_float2(c[i][j][0], c[i][j][1]);
            float2 v1 = make_float2(c[i][j][2], c[i][j][3]);
            if (bias) {
                const float2 bz = *(const float2*)&bias[col];
                v0.x += bz.x; v0.y += bz.y;
                v1.x += bz.x; v1.y += bz.y;
            }
            *(float2*)&C[(size_t)row * ND + col] = v0;
            *(float2*)&C[(size_t)(row + 8) * ND + col] = v1;
        }
    }
}

// ---------------------------------------------------------------------------
// Flash attention (R4 structure) + staggered cp.async single-buffer K/V:
// V(t) loads during QK(t); K(t+1) loads during PV(t).
// FIX vs R5/R6: full 16KB tile staged (4 chunks of 16B per thread, 1024 total).
// CTA = 128 queries x one (b,h), 8 warps, KV tiles of 64.
// Q/P pitch 68, K pitch 68, V pitch 72 [key][dim].
// ---------------------------------------------------------------------------
#define AQ_PITCH 68
#define AK_PITCH 68
#define AV_PITCH 72
// float offsets in dynamic smem
#define A_QS 0
#define A_KS 8704                     // 128*68
#define A_VS (8704 + 4352)            // + 64*68
#define A_PS (8704 + 4352 + 4608)     // + 64*72
#define A_TOT_FLOATS (A_PS + 8704)    // 26368 floats = 105472 bytes

__global__ __launch_bounds__(256, 2)
void attn_mma(const float* __restrict__ Q, const float* __restrict__ K,
              const float* __restrict__ V, float* __restrict__ O)
{
    extern __shared__ float sm[];
    const uint32_t sb = smem_u32(sm);
    float* Qs = sm + A_QS;
    float* Ks = sm + A_KS;
    float* Vs = sm + A_VS;
    float* Ps = sm + A_PS;

    const int tid = threadIdx.x;
    const int lane = tid & 31;
    const int wq = tid >> 5;
    const int r = lane >> 2, cq = lane & 3;

    const int bh = blockIdx.y;
    const int b = bh >> 3, h = bh & 7;
    const int q0 = blockIdx.x * 128;

    const float* Qb = Q + (size_t)(b * S1C + q0) * ND + h * 64;
    const float* Kb = K + (size_t)(b * S2C) * ND + h * 64;
    const float* Vb = V + (size_t)(b * S2C) * ND + h * 64;

    // full-tile staging: 64 rows x 16 segs of 16B = 1024 chunks, 4/thread
    auto issueK = [&](int kt) {
#pragma unroll
        for (int it = 0; it < 4; it++) {
            const int ch = tid + it * 256;
            const int row = ch >> 4, seg = ch & 15;
            cp16(sb + A_KS * 4 + row * (AK_PITCH * 4) + seg * 16,
                 Kb + (size_t)(kt * 64 + row) * ND + seg * 4);
        }
        CP_COMMIT();
    };
    auto issueV = [&](int kt) {
#pragma unroll
        for (int it = 0; it < 4; it++) {
            const int ch = tid + it * 256;
            const int row = ch >> 4, seg = ch & 15;
            cp16(sb + A_VS * 4 + row * (AV_PITCH * 4) + seg * 16,
                 Vb + (size_t)(kt * 64 + row) * ND + seg * 4);
        }
        CP_COMMIT();
    };

    // stage Q (scaled 1/8, rna->tf32), plain stores
#pragma unroll
    for (int it = 0; it < 8; it++) {
        const int q = tid + it * 256;
        const int row = q >> 4, seg = (q & 15) * 4;
        float4 v = *(const float4*)&Qb[(size_t)row * ND + seg];
        float4 o4;
        o4.x = to_tf32(v.x * 0.125f); o4.y = to_tf32(v.y * 0.125f);
        o4.z = to_tf32(v.z * 0.125f); o4.w = to_tf32(v.w * 0.125f);
        *(float4*)&Qs[row * AQ_PITCH + seg] = o4;
    }

    issueK(0);

    float o[8][4];
#pragma unroll
    for (int j = 0; j < 8; j++)
#pragma unroll
        for (int x = 0; x < 4; x++) o[j][x] = 0.f;
    float sum0 = 0.f, sum1 = 0.f;

    const int prow0 = wq * 16 + r;

    for (int kt = 0; kt < S2C / 64; kt++) {
        CP_WAIT0();          // K(t) complete (only K(t) outstanding here)
        __syncthreads();     // K(t) visible; PV(t-1) reads of Vs done

        issueV(kt);          // overlaps QK(t)

        // S = Q @ K^T
        float s8[8][4];
#pragma unroll
        for (int j = 0; j < 8; j++)
#pragma unroll
            for (int x = 0; x < 4; x++) s8[j][x] = 0.f;

#pragma unroll
        for (int kf = 0; kf < 8; kf++) {
            const int kc = kf * 8 + cq;
            uint32_t qa[4];
            qa[0] = __float_as_uint(Qs[prow0 * AQ_PITCH + kc]);
            qa[1] = __float_as_uint(Qs[(prow0 + 8) * AQ_PITCH + kc]);
            qa[2] = __float_as_uint(Qs[prow0 * AQ_PITCH + kc + 4]);
            qa[3] = __float_as_uint(Qs[(prow0 + 8) * AQ_PITCH + kc + 4]);
#pragma unroll
            for (int j = 0; j < 8; j++) {
                uint32_t kb2[2];
                kb2[0] = __float_as_uint(to_tf32(Ks[(j * 8 + r) * AK_PITCH + kc]));
                kb2[1] = __float_as_uint(to_tf32(Ks[(j * 8 + r) * AK_PITCH + kc + 4]));
                mma_tf32(s8[j], qa, kb2);
            }
        }

        // unshifted softmax partials
#pragma unroll
        for (int j = 0; j < 8; j++) {
            s8[j][0] = fast_exp(s8[j][0]);
            s8[j][1] = fast_exp(s8[j][1]);
            s8[j][2] = fast_exp(s8[j][2]);
            s8[j][3] = fast_exp(s8[j][3]);
            sum0 += s8[j][0] + s8[j][1];
            sum1 += s8[j][2] + s8[j][3];
        }

        CP_WAIT0();          // V(t) complete
        __syncthreads();     // V(t) visible; QK(t) reads of Ks done

        if (kt < S2C / 64 - 1) issueK(kt + 1);   // overlaps PV(t)

        // P -> smem (tf32), warp-private rows
        __syncwarp();
#pragma unroll
        for (int j = 0; j < 8; j++) {
            const int col = j * 8 + 2 * cq;
            Ps[prow0 * AQ_PITCH + col]           = to_tf32(s8[j][0]);
            Ps[prow0 * AQ_PITCH + col + 1]       = to_tf32(s8[j][1]);
            Ps[(prow0 + 8) * AQ_PITCH + col]     = to_tf32(s8[j][2]);
            Ps[(prow0 + 8) * AQ_PITCH + col + 1] = to_tf32(s8[j][3]);
        }
        __syncwarp();

        // O += P @ V
#pragma unroll
        for (int kf = 0; kf < 8; kf++) {
            const int kc = kf * 8 + cq;     // key index
            uint32_t pa[4];
            pa[0] = __float_as_uint(Ps[prow0 * AQ_PITCH + kc]);
            pa[1] = __float_as_uint(Ps[(prow0 + 8) * AQ_PITCH + kc]);
            pa[2] = __float_as_uint(Ps[prow0 * AQ_PITCH + kc + 4]);
            pa[3] = __float_as_uint(Ps[(prow0 + 8) * AQ_PITCH + kc + 4]);
#pragma unroll
            for (int j = 0; j < 8; j++) {
                uint32_t vb2[2];
                vb2[0] = __float_as_uint(to_tf32(Vs[kc * AV_PITCH + j * 8 + r]));
                vb2[1] = __float_as_uint(to_tf32(Vs[(kc + 4) * AV_PITCH + j * 8 + r]));
                mma_tf32(o[j], pa, vb2);
            }
        }
    }

    // quad-reduce row sums
    sum0 += __shfl_xor_sync(0xffffffffu, sum0, 1);
    sum0 += __shfl_xor_sync(0xffffffffu, sum0, 2);
    sum1 += __shfl_xor_sync(0xffffffffu, sum1, 1);
    sum1 += __shfl_xor_sync(0xffffffffu, sum1, 2);
    const float rl0 = 1.0f / sum0, rl1 = 1.0f / sum1;

    const int grow = b * S1C + q0 + wq * 16 + r;
#pragma unroll
    for (int j = 0; j < 8; j++) {
        const int col = h * 64 + j * 8 + 2 * cq;
        float2 v0 = make_float2(o[j][0] * rl0, o[j][1] * rl0);
        float2 v1 = make_float2(o[j][2] * rl1, o[j][3] * rl1);
        *(float2*)&O[(size_t)grow * ND + col] = v0;
        *(float2*)&O[(size_t)(grow + 8) * ND + col] = v1;
    }
}

// ---------------------------------------------------------------------------
// Launch
// ---------------------------------------------------------------------------
extern "C" void kernel_launch(void* const* d_in, const int* in_sizes, int n_in,
                              void* d_out, int out_size)
{
    (void)in_sizes; (void)n_in; (void)out_size;
    const float* x1 = (const float*)d_in[0];
    const float* x2 = (const float*)d_in[1];
    const float* x3 = (const float*)d_in[2];
    const float* Wq = (const float*)d_in[3];
    const float* Wk = (const float*)d_in[4];
    const float* Wv = (const float*)d_in[5];
    const float* Wo = (const float*)d_in[6];
    const float* bo = (const float*)d_in[7];
    float* out = (float*)d_out;

    float *Q, *K, *V, *A;
    cudaGetSymbolAddress((void**)&Q, g_Q);
    cudaGetSymbolAddress((void**)&K, g_K);
    cudaGetSymbolAddress((void**)&V, g_V);
    cudaGetSymbolAddress((void**)&A, g_ATT);
    __nv_bfloat16 *WTh, *WTl;
    cudaGetSymbolAddress((void**)&WTh, g_WTh);
    cudaGetSymbolAddress((void**)&WTl, g_WTl);

    cudaFuncSetAttribute(attn_mma, cudaFuncAttributeMaxDynamicSharedMemorySize,
                         A_TOT_FLOATS * 4);

    prep_w<<<dim3(16, 16, 4), 256>>>(Wq, Wk, Wv, Wo);

    const size_t WSZ = (size_t)KD * ND;
    dim3 gG(ND / 128, MROWS / 128);   // (4, 64)
    gemm_mma<<<gG, 256>>>(x1, WTh + 0 * WSZ, WTl + 0 * WSZ, nullptr, Q);
    gemm_mma<<<gG, 256>>>(x2, WTh + 1 * WSZ, WTl + 1 * WSZ, nullptr, K);
    gemm_mma<<<gG, 256>>>(x3, WTh + 2 * WSZ, WTl + 2 * WSZ, nullptr, V);

    dim3 gA(S1C / 128, BB * NH);      // (16, 32)
    attn_mma<<<gA, 256, A_TOT_FLOATS * 4>>>(Q, K, V, A);

    gemm_mma<<<gG, 256>>>(A, WTh + 3 * WSZ, WTl + 3 * WSZ, bo, out);
}

// round 8
// speedup vs baseline: 3.0407x; 1.0712x over previous
#include <cuda_runtime.h>
#include <cuda_bf16.h>
#include <cstdint>

// Problem constants
#define BB 4
#define S1C 2048
#define S2C 2048
#define NH 8
#define MROWS (BB * S1C)    // 8192
#define ND 512
#define KD 512

// Scratch (device globals — no allocation allowed)
__device__ float g_Q [MROWS * ND];
__device__ float g_K [MROWS * ND];
__device__ float g_V [MROWS * ND];
__device__ float g_ATT[MROWS * ND];
__device__ __nv_bfloat16 g_WTh[4 * (size_t)KD * ND];  // W^T [n][k] hi
__device__ __nv_bfloat16 g_WTl[4 * (size_t)KD * ND];  // W^T [n][k] lo residual

// ---------------------------------------------------------------------------
// helpers
// ---------------------------------------------------------------------------
__device__ __forceinline__ uint32_t smem_u32(const void* p) {
    uint32_t a;
    asm("{ .reg .u64 t; cvta.to.shared.u64 t, %1; cvt.u32.u64 %0, t; }"
        : "=r"(a) : "l"(p));
    return a;
}

__device__ __forceinline__ void cp16(uint32_t dst, const void* src) {
    asm volatile("cp.async.cg.shared.global [%0], [%1], 16;"
                 :: "r"(dst), "l"(src) : "memory");
}
#define CP_COMMIT() asm volatile("cp.async.commit_group;" ::: "memory")
#define CP_WAIT0()  asm volatile("cp.async.wait_group 0;" ::: "memory")

__device__ __forceinline__ float to_tf32(float x) {
    float y;
    asm("cvt.rna.tf32.f32 %0, %1;" : "=f"(y) : "f"(x));
    return y;
}

__device__ __forceinline__ void mma_bf16(float* c, const uint32_t* a, const uint32_t* b) {
    asm volatile(
        "mma.sync.aligned.m16n8k16.row.col.f32.bf16.bf16.f32 "
        "{%0,%1,%2,%3}, {%4,%5,%6,%7}, {%8,%9}, {%0,%1,%2,%3};"
        : "+f"(c[0]), "+f"(c[1]), "+f"(c[2]), "+f"(c[3])
        : "r"(a[0]), "r"(a[1]), "r"(a[2]), "r"(a[3]), "r"(b[0]), "r"(b[1]));
}

__device__ __forceinline__ void mma_tf32(float* c, const uint32_t* a, const uint32_t* b) {
    asm volatile(
        "mma.sync.aligned.m16n8k8.row.col.f32.tf32.tf32.f32 "
        "{%0,%1,%2,%3}, {%4,%5,%6,%7}, {%8,%9}, {%0,%1,%2,%3};"
        : "+f"(c[0]), "+f"(c[1]), "+f"(c[2]), "+f"(c[3])
        : "r"(a[0]), "r"(a[1]), "r"(a[2]), "r"(a[3]), "r"(b[0]), "r"(b[1]));
}

__device__ __forceinline__ uint32_t pack2(__nv_bfloat16 a, __nv_bfloat16 b) {
    return (uint32_t)__bfloat16_as_ushort(a) | ((uint32_t)__bfloat16_as_ushort(b) << 16);
}

// ---------------------------------------------------------------------------
// prep: W[k][n] (512x512 fp32) -> g_WTh/g_WTl [n][k] bf16 hi/lo
// Wq (z==0) additionally scaled by 1/8 (folds softmax 1/sqrt(64) into Q).
// ---------------------------------------------------------------------------
__global__ __launch_bounds__(256)
void prep_w(const float* __restrict__ Wq, const float* __restrict__ Wk,
            const float* __restrict__ Wv, const float* __restrict__ Wo)
{
    __shared__ float tbuf[32][33];
    const int z = blockIdx.z;
    const float* W = (z == 0) ? Wq : (z == 1) ? Wk : (z == 2) ? Wv : Wo;
    const float scale = (z == 0) ? 0.125f : 1.0f;
    __nv_bfloat16* oh = g_WTh + (size_t)z * KD * ND;
    __nv_bfloat16* ol = g_WTl + (size_t)z * KD * ND;
    const int k0 = blockIdx.x * 32, n0 = blockIdx.y * 32;
    const int lane = threadIdx.x & 31, r = threadIdx.x >> 5;

#pragma unroll
    for (int i = 0; i < 4; i++) {
        const int row = r + i * 8;
        tbuf[row][lane] = W[(size_t)(k0 + row) * ND + n0 + lane];
    }
    __syncthreads();
#pragma unroll
    for (int i = 0; i < 4; i++) {
        const int row = r + i * 8;
        const float x = tbuf[lane][row] * scale;
        const __nv_bfloat16 hb = __float2bfloat16(x);
        oh[(size_t)(n0 + row) * KD + k0 + lane] = hb;
        ol[(size_t)(n0 + row) * KD + k0 + lane] =
            __float2bfloat16(x - __bfloat162float(hb));
    }
}

// ---------------------------------------------------------------------------
// bf16x3 tensor-core GEMM body (R4-verified). ROUND_TF32: round output (for
// Q/K/V feeding the tf32 attention). Template over bias/rounding.
// ---------------------------------------------------------------------------
#define ASTR 40   // bf16 per smem row (32 + 8 pad)

template <bool ROUND_TF32, bool HAS_BIAS>
__device__ __forceinline__
void gemm_body(const float* __restrict__ A, const __nv_bfloat16* __restrict__ Bh,
               const __nv_bfloat16* __restrict__ Bl, const float* __restrict__ bias,
               float* __restrict__ C, int m0, int n0)
{
    __shared__ __nv_bfloat16 Ah[128 * ASTR], Al[128 * ASTR];
    __shared__ __nv_bfloat16 Bsh[128 * ASTR], Bsl[128 * ASTR];

    const int tid = threadIdx.x;
    const int lane = tid & 31;
    const int w = tid >> 5;
    const int wm = w & 1, wn = w >> 1;
    const int r = lane >> 2, cq = lane & 3;

    float c[4][4][4];
#pragma unroll
    for (int i = 0; i < 4; i++)
#pragma unroll
        for (int j = 0; j < 4; j++)
#pragma unroll
            for (int x = 0; x < 4; x++) c[i][j][x] = 0.f;

    float4 av[4];
    uint4 bvh[2], bvl[2];

#pragma unroll
    for (int it = 0; it < 4; it++) {
        const int q = tid + it * 256;
        av[it] = *(const float4*)&A[(size_t)(m0 + (q >> 3)) * KD + (q & 7) * 4];
    }
#pragma unroll
    for (int it = 0; it < 2; it++) {
        const int q = tid + it * 256;
        bvh[it] = *(const uint4*)&Bh[(size_t)(n0 + (q >> 2)) * KD + (q & 3) * 8];
        bvl[it] = *(const uint4*)&Bl[(size_t)(n0 + (q >> 2)) * KD + (q & 3) * 8];
    }

    for (int kt = 0; kt < 16; kt++) {
        __syncthreads();
#pragma unroll
        for (int it = 0; it < 4; it++) {
            const int q = tid + it * 256;
            const int row = q >> 3, kq = (q & 7) * 4;
            const float4 v = av[it];
            __nv_bfloat16 h0 = __float2bfloat16(v.x), h1 = __float2bfloat16(v.y),
                          h2 = __float2bfloat16(v.z), h3 = __float2bfloat16(v.w);
            uint2 ph = make_uint2(pack2(h0, h1), pack2(h2, h3));
            uint2 pl = make_uint2(
                pack2(__float2bfloat16(v.x - __bfloat162float(h0)),
                      __float2bfloat16(v.y - __bfloat162float(h1))),
                pack2(__float2bfloat16(v.z - __bfloat162float(h2)),
                      __float2bfloat16(v.w - __bfloat162float(h3))));
            *(uint2*)&Ah[row * ASTR + kq] = ph;
            *(uint2*)&Al[row * ASTR + kq] = pl;
        }
#pragma unroll
        for (int it = 0; it < 2; it++) {
            const int q = tid + it * 256;
            const int row = q >> 2, seg = (q & 3) * 8;
            *(uint4*)&Bsh[row * ASTR + seg] = bvh[it];
            *(uint4*)&Bsl[row * ASTR + seg] = bvl[it];
        }
        __syncthreads();

        if (kt < 15) {
            const int k0 = (kt + 1) * 32;
#pragma unroll
            for (int it = 0; it < 4; it++) {
                const int q = tid + it * 256;
                av[it] = *(const float4*)&A[(size_t)(m0 + (q >> 3)) * KD + k0 + (q & 7) * 4];
            }
#pragma unroll
            for (int it = 0; it < 2; it++) {
                const int q = tid + it * 256;
                bvh[it] = *(const uint4*)&Bh[(size_t)(n0 + (q >> 2)) * KD + k0 + (q & 3) * 8];
                bvl[it] = *(const uint4*)&Bl[(size_t)(n0 + (q >> 2)) * KD + k0 + (q & 3) * 8];
            }
        }

#pragma unroll
        for (int ks = 0; ks < 2; ks++) {
            const int kb = ks * 16 + 2 * cq;
            uint32_t ah[4][4], al4[4][4];
#pragma unroll
            for (int i = 0; i < 4; i++) {
                const int row = wm * 64 + i * 16 + r;
                ah[i][0] = *(const uint32_t*)&Ah[row * ASTR + kb];
                ah[i][1] = *(const uint32_t*)&Ah[(row + 8) * ASTR + kb];
                ah[i][2] = *(const uint32_t*)&Ah[row * ASTR + kb + 8];
                ah[i][3] = *(const uint32_t*)&Ah[(row + 8) * ASTR + kb + 8];
                al4[i][0] = *(const uint32_t*)&Al[row * ASTR + kb];
                al4[i][1] = *(const uint32_t*)&Al[(row + 8) * ASTR + kb];
                al4[i][2] = *(const uint32_t*)&Al[row * ASTR + kb + 8];
                al4[i][3] = *(const uint32_t*)&Al[(row + 8) * ASTR + kb + 8];
            }
#pragma unroll
            for (int j = 0; j < 4; j++) {
                const int n = wn * 32 + j * 8 + r;
                uint32_t bh2[2] = { *(const uint32_t*)&Bsh[n * ASTR + kb],
                                    *(const uint32_t*)&Bsh[n * ASTR + kb + 8] };
                uint32_t bl2[2] = { *(const uint32_t*)&Bsl[n * ASTR + kb],
                                    *(const uint32_t*)&Bsl[n * ASTR + kb + 8] };
#pragma unroll
                for (int i = 0; i < 4; i++) {
                    mma_bf16(c[i][j], ah[i], bh2);
                    mma_bf16(c[i][j], ah[i], bl2);
                    mma_bf16(c[i][j], al4[i], bh2);
                }
            }
        }
    }

#pragma unroll
    for (int i = 0; i < 4; i++) {
        const int row = m0 + wm * 64 + i * 16 + r;
#pragma unroll
        for (int j = 0; j < 4; j++) {
            const int col = n0 + wn * 32 + j * 8 + 2 * cq;
            float2 v0 = make_float2(c[i][j][0], c[i][j][1]);
            float2 v1 = make_float2(c[i][j][2], c[i][j][3]);
            if (HAS_BIAS) {
                const float2 bz = *(const float2*)&bias[col];
                v0.x += bz.x; v0.y += bz.y;
                v1.x += bz.x; v1.y += bz.y;
            }
            if (ROUND_TF32) {
                v0.x = to_tf32(v0.x); v0.y = to_tf32(v0.y);
                v1.x = to_tf32(v1.x); v1.y = to_tf32(v1.y);
            }
            *(float2*)&C[(size_t)row * ND + col] = v0;
            *(float2*)&C[(size_t)(row + 8) * ND + col] = v1;
        }
    }
}

// Merged Q/K/V projection: blockIdx.z selects input/weight/output.
__global__ __launch_bounds__(256)
void qkv_mma(const float* __restrict__ x1, const float* __restrict__ x2,
             const float* __restrict__ x3)
{
    const int z = blockIdx.z;
    const float* A = (z == 0) ? x1 : (z == 1) ? x2 : x3;
    float* C = (z == 0) ? g_Q : (z == 1) ? g_K : g_V;
    const __nv_bfloat16* Bh = g_WTh + (size_t)z * KD * ND;
    const __nv_bfloat16* Bl = g_WTl + (size_t)z * KD * ND;
    gemm_body<true, false>(A, Bh, Bl, nullptr, C,
                           blockIdx.y * 128, blockIdx.x * 128);
}

// Output projection with bias.
__global__ __launch_bounds__(256)
void out_mma(const float* __restrict__ bias, float* __restrict__ C)
{
    const __nv_bfloat16* Bh = g_WTh + (size_t)3 * KD * ND;
    const __nv_bfloat16* Bl = g_WTl + (size_t)3 * KD * ND;
    gemm_body<false, true>(g_ATT, Bh, Bl, bias, C,
                           blockIdx.y * 128, blockIdx.x * 128);
}

// ---------------------------------------------------------------------------
// Flash attention. Q/K/V arrive pre-rounded to tf32 (and Q pre-scaled), so
// fragments load raw — no cvt in the hot loop. exp via MUFU (__expf).
// Staggered cp.async: Q+K(0) up front; V(t) under QK(t); K(t+1) under PV(t).
// ---------------------------------------------------------------------------
#define AQ_PITCH 68
#define AK_PITCH 68
#define AV_PITCH 72
#define A_QS 0
#define A_KS 8704                     // 128*68
#define A_VS (8704 + 4352)            // + 64*68
#define A_PS (8704 + 4352 + 4608)     // + 64*72
#define A_TOT_FLOATS (A_PS + 8704)    // 26368 floats = 105472 bytes

__global__ __launch_bounds__(256, 2)
void attn_mma(const float* __restrict__ Q, const float* __restrict__ K,
              const float* __restrict__ V, float* __restrict__ O)
{
    extern __shared__ float sm[];
    const uint32_t sb = smem_u32(sm);
    float* Qs = sm + A_QS;
    float* Ks = sm + A_KS;
    float* Vs = sm + A_VS;
    float* Ps = sm + A_PS;

    const int tid = threadIdx.x;
    const int lane = tid & 31;
    const int wq = tid >> 5;
    const int r = lane >> 2, cq = lane & 3;

    const int bh = blockIdx.y;
    const int b = bh >> 3, h = bh & 7;
    const int q0 = blockIdx.x * 128;

    const float* Qb = Q + (size_t)(b * S1C + q0) * ND + h * 64;
    const float* Kb = K + (size_t)(b * S2C) * ND + h * 64;
    const float* Vb = V + (size_t)(b * S2C) * ND + h * 64;

    auto issueK = [&](int kt) {
#pragma unroll
        for (int it = 0; it < 4; it++) {
            const int ch = tid + it * 256;
            const int row = ch >> 4, seg = ch & 15;
            cp16(sb + A_KS * 4 + row * (AK_PITCH * 4) + seg * 16,
                 Kb + (size_t)(kt * 64 + row) * ND + seg * 4);
        }
        CP_COMMIT();
    };
    auto issueV = [&](int kt) {
#pragma unroll
        for (int it = 0; it < 4; it++) {
            const int ch = tid + it * 256;
            const int row = ch >> 4, seg = ch & 15;
            cp16(sb + A_VS * 4 + row * (AV_PITCH * 4) + seg * 16,
                 Vb + (size_t)(kt * 64 + row) * ND + seg * 4);
        }
        CP_COMMIT();
    };

    // stage Q via cp.async (pure copy — already scaled + tf32-rounded)
#pragma unroll
    for (int it = 0; it < 8; it++) {
        const int ch = tid + it * 256;        // 0..2047
        const int row = ch >> 4, seg = ch & 15;
        cp16(sb + A_QS * 4 + row * (AQ_PITCH * 4) + seg * 16,
             Qb + (size_t)row * ND + seg * 4);
    }
    CP_COMMIT();
    issueK(0);

    float o[8][4];
#pragma unroll
    for (int j = 0; j < 8; j++)
#pragma unroll
        for (int x = 0; x < 4; x++) o[j][x] = 0.f;
    float sum0 = 0.f, sum1 = 0.f;

    const int prow0 = wq * 16 + r;

    for (int kt = 0; kt < S2C / 64; kt++) {
        CP_WAIT0();          // K(t) (+Q on t=0) complete
        __syncthreads();     // visible; PV(t-1) reads of Vs done

        issueV(kt);          // overlaps QK(t)

        float s8[8][4];
#pragma unroll
        for (int j = 0; j < 8; j++)
#pragma unroll
            for (int x = 0; x < 4; x++) s8[j][x] = 0.f;

#pragma unroll
        for (int kf = 0; kf < 8; kf++) {
            const int kc = kf * 8 + cq;
            uint32_t qa[4];
            qa[0] = __float_as_uint(Qs[prow0 * AQ_PITCH + kc]);
            qa[1] = __float_as_uint(Qs[(prow0 + 8) * AQ_PITCH + kc]);
            qa[2] = __float_as_uint(Qs[prow0 * AQ_PITCH + kc + 4]);
            qa[3] = __float_as_uint(Qs[(prow0 + 8) * AQ_PITCH + kc + 4]);
#pragma unroll
            for (int j = 0; j < 8; j++) {
                uint32_t kb2[2];
                kb2[0] = __float_as_uint(Ks[(j * 8 + r) * AK_PITCH + kc]);
                kb2[1] = __float_as_uint(Ks[(j * 8 + r) * AK_PITCH + kc + 4]);
                mma_tf32(s8[j], qa, kb2);
            }
        }

        // unshifted softmax partials (MUFU exp)
#pragma unroll
        for (int j = 0; j < 8; j++) {
            s8[j][0] = __expf(s8[j][0]);
            s8[j][1] = __expf(s8[j][1]);
            s8[j][2] = __expf(s8[j][2]);
            s8[j][3] = __expf(s8[j][3]);
            sum0 += s8[j][0] + s8[j][1];
            sum1 += s8[j][2] + s8[j][3];
        }

        CP_WAIT0();          // V(t) complete
        __syncthreads();     // visible; QK(t) reads of Ks done

        if (kt < S2C / 64 - 1) issueK(kt + 1);   // overlaps PV(t)

        // P -> smem (tf32), warp-private rows
        __syncwarp();
#pragma unroll
        for (int j = 0; j < 8; j++) {
            const int col = j * 8 + 2 * cq;
            Ps[prow0 * AQ_PITCH + col]           = to_tf32(s8[j][0]);
            Ps[prow0 * AQ_PITCH + col + 1]       = to_tf32(s8[j][1]);
            Ps[(prow0 + 8) * AQ_PITCH + col]     = to_tf32(s8[j][2]);
            Ps[(prow0 + 8) * AQ_PITCH + col + 1] = to_tf32(s8[j][3]);
        }
        __syncwarp();

        // O += P @ V
#pragma unroll
        for (int kf = 0; kf < 8; kf++) {
            const int kc = kf * 8 + cq;
            uint32_t pa[4];
            pa[0] = __float_as_uint(Ps[prow0 * AQ_PITCH + kc]);
            pa[1] = __float_as_uint(Ps[(prow0 + 8) * AQ_PITCH + kc]);
            pa[2] = __float_as_uint(Ps[prow0 * AQ_PITCH + kc + 4]);
            pa[3] = __float_as_uint(Ps[(prow0 + 8) * AQ_PITCH + kc + 4]);
#pragma unroll
            for (int j = 0; j < 8; j++) {
                uint32_t vb2[2];
                vb2[0] = __float_as_uint(Vs[kc * AV_PITCH + j * 8 + r]);
                vb2[1] = __float_as_uint(Vs[(kc + 4) * AV_PITCH + j * 8 + r]);
                mma_tf32(o[j], pa, vb2);
            }
        }
    }

    sum0 += __shfl_xor_sync(0xffffffffu, sum0, 1);
    sum0 += __shfl_xor_sync(0xffffffffu, sum0, 2);
    sum1 += __shfl_xor_sync(0xffffffffu, sum1, 1);
    sum1 += __shfl_xor_sync(0xffffffffu, sum1, 2);
    const float rl0 = 1.0f / sum0, rl1 = 1.0f / sum1;

    const int grow = b * S1C + q0 + wq * 16 + r;
#pragma unroll
    for (int j = 0; j < 8; j++) {
        const int col = h * 64 + j * 8 + 2 * cq;
        float2 v0 = make_float2(o[j][0] * rl0, o[j][1] * rl0);
        float2 v1 = make_float2(o[j][2] * rl1, o[j][3] * rl1);
        *(float2*)&O[(size_t)grow * ND + col] = v0;
        *(float2*)&O[(size_t)(grow + 8) * ND + col] = v1;
    }
}

// ---------------------------------------------------------------------------
// Launch
// ---------------------------------------------------------------------------
extern "C" void kernel_launch(void* const* d_in, const int* in_sizes, int n_in,
                              void* d_out, int out_size)
{
    (void)in_sizes; (void)n_in; (void)out_size;
    const float* x1 = (const float*)d_in[0];
    const float* x2 = (const float*)d_in[1];
    const float* x3 = (const float*)d_in[2];
    const float* Wq = (const float*)d_in[3];
    const float* Wk = (const float*)d_in[4];
    const float* Wv = (const float*)d_in[5];
    const float* Wo = (const float*)d_in[6];
    const float* bo = (const float*)d_in[7];
    float* out = (float*)d_out;

    float *Q, *K, *V;
    cudaGetSymbolAddress((void**)&Q, g_Q);
    cudaGetSymbolAddress((void**)&K, g_K);
    cudaGetSymbolAddress((void**)&V, g_V);
    float* A;
    cudaGetSymbolAddress((void**)&A, g_ATT);

    cudaFuncSetAttribute(attn_mma, cudaFuncAttributeMaxDynamicSharedMemorySize,
                         A_TOT_FLOATS * 4);

    prep_w<<<dim3(16, 16, 4), 256>>>(Wq, Wk, Wv, Wo);

    dim3 gQKV(ND / 128, MROWS / 128, 3);   // (4, 64, 3)
    qkv_mma<<<gQKV, 256>>>(x1, x2, x3);

    dim3 gA(S1C / 128, BB * NH);           // (16, 32)
    attn_mma<<<gA, 256, A_TOT_FLOATS * 4>>>(Q, K, V, A);

    dim3 gO(ND / 128, MROWS / 128);        // (4, 64)
    out_mma<<<gO, 256>>>(bo, out);
}

// round 9
// speedup vs baseline: 3.2095x; 1.0555x over previous
#include <cuda_runtime.h>
#include <cuda_bf16.h>
#include <cstdint>

// Problem constants
#define BB 4
#define S1C 2048
#define S2C 2048
#define NH 8
#define MROWS (BB * S1C)    // 8192
#define ND 512
#define KD 512

// Scratch (device globals — no allocation allowed)
__device__ float g_Q [MROWS * ND];
__device__ float g_K [MROWS * ND];
__device__ float g_V [MROWS * ND];
__device__ float g_ATT[MROWS * ND];
__device__ __nv_bfloat16 g_WTh[4 * (size_t)KD * ND];  // W^T [n][k] hi
__device__ __nv_bfloat16 g_WTl[4 * (size_t)KD * ND];  // W^T [n][k] lo residual

// ---------------------------------------------------------------------------
// helpers
// ---------------------------------------------------------------------------
__device__ __forceinline__ uint32_t smem_u32(const void* p) {
    uint32_t a;
    asm("{ .reg .u64 t; cvta.to.shared.u64 t, %1; cvt.u32.u64 %0, t; }"
        : "=r"(a) : "l"(p));
    return a;
}

__device__ __forceinline__ void cp16(uint32_t dst, const void* src) {
    asm volatile("cp.async.cg.shared.global [%0], [%1], 16;"
                 :: "r"(dst), "l"(src) : "memory");
}
#define CP_COMMIT() asm volatile("cp.async.commit_group;" ::: "memory")
#define CP_WAIT0()  asm volatile("cp.async.wait_group 0;" ::: "memory")
#define CP_WAIT1()  asm volatile("cp.async.wait_group 1;" ::: "memory")

__device__ __forceinline__ float to_tf32(float x) {
    float y;
    asm("cvt.rna.tf32.f32 %0, %1;" : "=f"(y) : "f"(x));
    return y;
}

__device__ __forceinline__ void mma_bf16(float* c, const uint32_t* a, const uint32_t* b) {
    asm volatile(
        "mma.sync.aligned.m16n8k16.row.col.f32.bf16.bf16.f32 "
        "{%0,%1,%2,%3}, {%4,%5,%6,%7}, {%8,%9}, {%0,%1,%2,%3};"
        : "+f"(c[0]), "+f"(c[1]), "+f"(c[2]), "+f"(c[3])
        : "r"(a[0]), "r"(a[1]), "r"(a[2]), "r"(a[3]), "r"(b[0]), "r"(b[1]));
}

__device__ __forceinline__ void mma_tf32(float* c, const uint32_t* a, const uint32_t* b) {
    asm volatile(
        "mma.sync.aligned.m16n8k8.row.col.f32.tf32.tf32.f32 "
        "{%0,%1,%2,%3}, {%4,%5,%6,%7}, {%8,%9}, {%0,%1,%2,%3};"
        : "+f"(c[0]), "+f"(c[1]), "+f"(c[2]), "+f"(c[3])
        : "r"(a[0]), "r"(a[1]), "r"(a[2]), "r"(a[3]), "r"(b[0]), "r"(b[1]));
}

__device__ __forceinline__ uint32_t pack2(__nv_bfloat16 a, __nv_bfloat16 b) {
    return (uint32_t)__bfloat16_as_ushort(a) | ((uint32_t)__bfloat16_as_ushort(b) << 16);
}

// split a float2 into packed bf16x2 hi and lo-residual
__device__ __forceinline__ void split2(float x, float y, uint32_t& hi, uint32_t& lo) {
    __nv_bfloat16 h0 = __float2bfloat16(x), h1 = __float2bfloat16(y);
    hi = pack2(h0, h1);
    lo = pack2(__float2bfloat16(x - __bfloat162float(h0)),
               __float2bfloat16(y - __bfloat162float(h1)));
}

// ---------------------------------------------------------------------------
// prep: W[k][n] (512x512 fp32) -> g_WTh/g_WTl [n][k] bf16 hi/lo
// Wq (z==0) additionally scaled by 1/8 (folds softmax 1/sqrt(64) into Q).
// ---------------------------------------------------------------------------
__global__ __launch_bounds__(256)
void prep_w(const float* __restrict__ Wq, const float* __restrict__ Wk,
            const float* __restrict__ Wv, const float* __restrict__ Wo)
{
    __shared__ float tbuf[32][33];
    const int z = blockIdx.z;
    const float* W = (z == 0) ? Wq : (z == 1) ? Wk : (z == 2) ? Wv : Wo;
    const float scale = (z == 0) ? 0.125f : 1.0f;
    __nv_bfloat16* oh = g_WTh + (size_t)z * KD * ND;
    __nv_bfloat16* ol = g_WTl + (size_t)z * KD * ND;
    const int k0 = blockIdx.x * 32, n0 = blockIdx.y * 32;
    const int lane = threadIdx.x & 31, r = threadIdx.x >> 5;

#pragma unroll
    for (int i = 0; i < 4; i++) {
        const int row = r + i * 8;
        tbuf[row][lane] = W[(size_t)(k0 + row) * ND + n0 + lane];
    }
    __syncthreads();
#pragma unroll
    for (int i = 0; i < 4; i++) {
        const int row = r + i * 8;
        const float x = tbuf[lane][row] * scale;
        const __nv_bfloat16 hb = __float2bfloat16(x);
        oh[(size_t)(n0 + row) * KD + k0 + lane] = hb;
        ol[(size_t)(n0 + row) * KD + k0 + lane] =
            __float2bfloat16(x - __bfloat162float(hb));
    }
}

// ---------------------------------------------------------------------------
// bf16x3 tensor-core GEMM, cp.async double-buffered, 2 CTAs/SM.
// A staged raw fp32 (pitch 40 fl); hi/lo split at fragment-load (FMA pipe idle).
// B bf16 (pitch 56). CTA 128x128, 8 warps (2m x 4n), BK=32.
// ---------------------------------------------------------------------------
#define GA_PITCH 40            // floats
#define GB_PITCH 56            // bf16
// byte offsets in dynamic smem
#define G_A0  0
#define G_A1  20480            // 128*160
#define G_BH0 40960
#define G_BH1 55296            // +128*112
#define G_BL0 69632
#define G_BL1 83968
#define G_TOTAL 98304          // 96 KB -> 2 CTAs/SM

template <bool ROUND_TF32, bool HAS_BIAS>
__device__ __forceinline__
void gemm_body(const float* __restrict__ A, const __nv_bfloat16* __restrict__ Bh,
               const __nv_bfloat16* __restrict__ Bl, const float* __restrict__ bias,
               float* __restrict__ C, int m0, int n0, char* smc)
{
    const uint32_t sb = smem_u32(smc);
    const int tid = threadIdx.x;
    const int lane = tid & 31;
    const int w = tid >> 5;
    const int wm = w & 1, wn = w >> 1;
    const int r = lane >> 2, cq = lane & 3;

    float c[4][4][4];
#pragma unroll
    for (int i = 0; i < 4; i++)
#pragma unroll
        for (int j = 0; j < 4; j++)
#pragma unroll
            for (int x = 0; x < 4; x++) c[i][j][x] = 0.f;

    auto issue = [&](int kt, int buf) {
        const int k0 = kt * 32;
        const uint32_t ab = sb + (buf ? G_A1 : G_A0);
        const uint32_t hb = sb + (buf ? G_BH1 : G_BH0);
        const uint32_t lb = sb + (buf ? G_BL1 : G_BL0);
#pragma unroll
        for (int it = 0; it < 4; it++) {
            const int ch = tid + it * 256;            // 0..1023
            const int row = ch >> 3, seg = ch & 7;
            cp16(ab + row * 160 + seg * 16,
                 A + (size_t)(m0 + row) * KD + k0 + seg * 4);
        }
#pragma unroll
        for (int it = 0; it < 2; it++) {
            const int ch = tid + it * 256;            // 0..511
            const int row = ch >> 2, seg = ch & 3;
            cp16(hb + row * 112 + seg * 16,
                 Bh + (size_t)(n0 + row) * KD + k0 + seg * 8);
            cp16(lb + row * 112 + seg * 16,
                 Bl + (size_t)(n0 + row) * KD + k0 + seg * 8);
        }
        CP_COMMIT();
    };

    issue(0, 0);

    for (int kt = 0; kt < 16; kt++) {
        if (kt < 15) { issue(kt + 1, (kt + 1) & 1); CP_WAIT1(); }
        else         { CP_WAIT0(); }
        __syncthreads();

        const int buf = kt & 1;
        const float* As = (const float*)(smc + (buf ? G_A1 : G_A0));
        const __nv_bfloat16* Bhs = (const __nv_bfloat16*)(smc + (buf ? G_BH1 : G_BH0));
        const __nv_bfloat16* Bls = (const __nv_bfloat16*)(smc + (buf ? G_BL1 : G_BL0));

#pragma unroll
        for (int ks = 0; ks < 2; ks++) {
            const int c0 = ks * 16 + 2 * cq;
            uint32_t ah[4][4], al[4][4];
#pragma unroll
            for (int i = 0; i < 4; i++) {
                const int row0 = wm * 64 + i * 16 + r;
                float2 v0 = *(const float2*)&As[row0 * GA_PITCH + c0];
                float2 v1 = *(const float2*)&As[(row0 + 8) * GA_PITCH + c0];
                float2 v2 = *(const float2*)&As[row0 * GA_PITCH + c0 + 8];
                float2 v3 = *(const float2*)&As[(row0 + 8) * GA_PITCH + c0 + 8];
                split2(v0.x, v0.y, ah[i][0], al[i][0]);
                split2(v1.x, v1.y, ah[i][1], al[i][1]);
                split2(v2.x, v2.y, ah[i][2], al[i][2]);
                split2(v3.x, v3.y, ah[i][3], al[i][3]);
            }
#pragma unroll
            for (int j = 0; j < 4; j++) {
                const int n = wn * 32 + j * 8 + r;
                const int kb = ks * 16 + 2 * cq;
                uint32_t bh2[2] = { *(const uint32_t*)&Bhs[n * GB_PITCH + kb],
                                    *(const uint32_t*)&Bhs[n * GB_PITCH + kb + 8] };
                uint32_t bl2[2] = { *(const uint32_t*)&Bls[n * GB_PITCH + kb],
                                    *(const uint32_t*)&Bls[n * GB_PITCH + kb + 8] };
#pragma unroll
                for (int i = 0; i < 4; i++) {
                    mma_bf16(c[i][j], ah[i], bh2);
                    mma_bf16(c[i][j], ah[i], bl2);
                    mma_bf16(c[i][j], al[i], bh2);
                }
            }
        }
        __syncthreads();   // all reads of buf done before it is re-filled
    }

#pragma unroll
    for (int i = 0; i < 4; i++) {
        const int row = m0 + wm * 64 + i * 16 + r;
#pragma unroll
        for (int j = 0; j < 4; j++) {
            const int col = n0 + wn * 32 + j * 8 + 2 * cq;
            float2 v0 = make_float2(c[i][j][0], c[i][j][1]);
            float2 v1 = make_float2(c[i][j][2], c[i][j][3]);
            if (HAS_BIAS) {
                const float2 bz = *(const float2*)&bias[col];
                v0.x += bz.x; v0.y += bz.y;
                v1.x += bz.x; v1.y += bz.y;
            }
            if (ROUND_TF32) {
                v0.x = to_tf32(v0.x); v0.y = to_tf32(v0.y);
                v1.x = to_tf32(v1.x); v1.y = to_tf32(v1.y);
            }
            *(float2*)&C[(size_t)row * ND + col] = v0;
            *(float2*)&C[(size_t)(row + 8) * ND + col] = v1;
        }
    }
}

// Merged Q/K/V projection: blockIdx.z selects input/weight/output.
__global__ __launch_bounds__(256, 2)
void qkv_mma(const float* __restrict__ x1, const float* __restrict__ x2,
             const float* __restrict__ x3)
{
    extern __shared__ char smc[];
    const int z = blockIdx.z;
    const float* A = (z == 0) ? x1 : (z == 1) ? x2 : x3;
    float* C = (z == 0) ? g_Q : (z == 1) ? g_K : g_V;
    const __nv_bfloat16* Bh = g_WTh + (size_t)z * KD * ND;
    const __nv_bfloat16* Bl = g_WTl + (size_t)z * KD * ND;
    gemm_body<true, false>(A, Bh, Bl, nullptr, C,
                           blockIdx.y * 128, blockIdx.x * 128, smc);
}

// Output projection with bias.
__global__ __launch_bounds__(256, 2)
void out_mma(const float* __restrict__ bias, float* __restrict__ C)
{
    extern __shared__ char smc[];
    const __nv_bfloat16* Bh = g_WTh + (size_t)3 * KD * ND;
    const __nv_bfloat16* Bl = g_WTl + (size_t)3 * KD * ND;
    gemm_body<false, true>(g_ATT, Bh, Bl, bias, C,
                           blockIdx.y * 128, blockIdx.x * 128, smc);
}

// ---------------------------------------------------------------------------
// Flash attention. Q/K/V pre-rounded tf32 (Q pre-scaled). Q fragments hoisted
// to registers once per CTA. Staggered cp.async: V(t) under QK(t), K(t+1)
// under PV(t).
// ---------------------------------------------------------------------------
#define AQ_PITCH 68
#define AK_PITCH 68
#define AV_PITCH 72
#define A_QS 0
#define A_KS 8704                     // 128*68
#define A_VS (8704 + 4352)            // + 64*68
#define A_PS (8704 + 4352 + 4608)     // + 64*72
#define A_TOT_FLOATS (A_PS + 8704)    // 26368 floats = 105472 bytes

__global__ __launch_bounds__(256, 2)
void attn_mma(const float* __restrict__ Q, const float* __restrict__ K,
              const float* __restrict__ V, float* __restrict__ O)
{
    extern __shared__ float sm[];
    const uint32_t sb = smem_u32(sm);
    float* Qs = sm + A_QS;
    float* Ks = sm + A_KS;
    float* Vs = sm + A_VS;
    float* Ps = sm + A_PS;

    const int tid = threadIdx.x;
    const int lane = tid & 31;
    const int wq = tid >> 5;
    const int r = lane >> 2, cq = lane & 3;

    const int bh = blockIdx.y;
    const int b = bh >> 3, h = bh & 7;
    const int q0 = blockIdx.x * 128;

    const float* Qb = Q + (size_t)(b * S1C + q0) * ND + h * 64;
    const float* Kb = K + (size_t)(b * S2C) * ND + h * 64;
    const float* Vb = V + (size_t)(b * S2C) * ND + h * 64;

    auto issueK = [&](int kt) {
#pragma unroll
        for (int it = 0; it < 4; it++) {
            const int ch = tid + it * 256;
            const int row = ch >> 4, seg = ch & 15;
            cp16(sb + A_KS * 4 + row * (AK_PITCH * 4) + seg * 16,
                 Kb + (size_t)(kt * 64 + row) * ND + seg * 4);
        }
        CP_COMMIT();
    };
    auto issueV = [&](int kt) {
#pragma unroll
        for (int it = 0; it < 4; it++) {
            const int ch = tid + it * 256;
            const int row = ch >> 4, seg = ch & 15;
            cp16(sb + A_VS * 4 + row * (AV_PITCH * 4) + seg * 16,
                 Vb + (size_t)(kt * 64 + row) * ND + seg * 4);
        }
        CP_COMMIT();
    };

    // stage Q via cp.async (already scaled + tf32-rounded)
#pragma unroll
    for (int it = 0; it < 8; it++) {
        const int ch = tid + it * 256;        // 0..2047
        const int row = ch >> 4, seg = ch & 15;
        cp16(sb + A_QS * 4 + row * (AQ_PITCH * 4) + seg * 16,
             Qb + (size_t)row * ND + seg * 4);
    }
    CP_COMMIT();
    issueK(0);

    // wait for Q (+K0), then hoist Q fragments into registers
    CP_WAIT0();
    __syncthreads();
    const int prow0 = wq * 16 + r;
    uint32_t qa[8][4];
#pragma unroll
    for (int kf = 0; kf < 8; kf++) {
        const int kc = kf * 8 + cq;
        qa[kf][0] = __float_as_uint(Qs[prow0 * AQ_PITCH + kc]);
        qa[kf][1] = __float_as_uint(Qs[(prow0 + 8) * AQ_PITCH + kc]);
        qa[kf][2] = __float_as_uint(Qs[prow0 * AQ_PITCH + kc + 4]);
        qa[kf][3] = __float_as_uint(Qs[(prow0 + 8) * AQ_PITCH + kc + 4]);
    }

    float o[8][4];
#pragma unroll
    for (int j = 0; j < 8; j++)
#pragma unroll
        for (int x = 0; x < 4; x++) o[j][x] = 0.f;
    float sum0 = 0.f, sum1 = 0.f;

    for (int kt = 0; kt < S2C / 64; kt++) {
        CP_WAIT0();          // K(t) complete (no-op at kt=0)
        __syncthreads();     // visible; PV(t-1) reads of Vs done

        issueV(kt);          // overlaps QK(t)

        float s8[8][4];
#pragma unroll
        for (int j = 0; j < 8; j++)
#pragma unroll
            for (int x = 0; x < 4; x++) s8[j][x] = 0.f;

#pragma unroll
        for (int kf = 0; kf < 8; kf++) {
            const int kc = kf * 8 + cq;
#pragma unroll
            for (int j = 0; j < 8; j++) {
                uint32_t kb2[2];
                kb2[0] = __float_as_uint(Ks[(j * 8 + r) * AK_PITCH + kc]);
                kb2[1] = __float_as_uint(Ks[(j * 8 + r) * AK_PITCH + kc + 4]);
                mma_tf32(s8[j], qa[kf], kb2);
            }
        }

        // unshifted softmax partials (MUFU exp)
#pragma unroll
        for (int j = 0; j < 8; j++) {
            s8[j][0] = __expf(s8[j][0]);
            s8[j][1] = __expf(s8[j][1]);
            s8[j][2] = __expf(s8[j][2]);
            s8[j][3] = __expf(s8[j][3]);
            sum0 += s8[j][0] + s8[j][1];
            sum1 += s8[j][2] + s8[j][3];
        }

        CP_WAIT0();          // V(t) complete
        __syncthreads();     // visible; QK(t) reads of Ks done

        if (kt < S2C / 64 - 1) issueK(kt + 1);   // overlaps PV(t)

        // P -> smem (tf32), warp-private rows
        __syncwarp();
#pragma unroll
        for (int j = 0; j < 8; j++) {
            const int col = j * 8 + 2 * cq;
            Ps[prow0 * AQ_PITCH + col]           = to_tf32(s8[j][0]);
            Ps[prow0 * AQ_PITCH + col + 1]       = to_tf32(s8[j][1]);
            Ps[(prow0 + 8) * AQ_PITCH + col]     = to_tf32(s8[j][2]);
            Ps[(prow0 + 8) * AQ_PITCH + col + 1] = to_tf32(s8[j][3]);
        }
        __syncwarp();

        // O += P @ V
#pragma unroll
        for (int kf = 0; kf < 8; kf++) {
            const int kc = kf * 8 + cq;
            uint32_t pa[4];
            pa[0] = __float_as_uint(Ps[prow0 * AQ_PITCH + kc]);
            pa[1] = __float_as_uint(Ps[(prow0 + 8) * AQ_PITCH + kc]);
            pa[2] = __float_as_uint(Ps[prow0 * AQ_PITCH + kc + 4]);
            pa[3] = __float_as_uint(Ps[(prow0 + 8) * AQ_PITCH + kc + 4]);
#pragma unroll
            for (int j = 0; j < 8; j++) {
                uint32_t vb2[2];
                vb2[0] = __float_as_uint(Vs[kc * AV_PITCH + j * 8 + r]);
                vb2[1] = __float_as_uint(Vs[(kc + 4) * AV_PITCH + j * 8 + r]);
                mma_tf32(o[j], pa, vb2);
            }
        }
    }

    sum0 += __shfl_xor_sync(0xffffffffu, sum0, 1);
    sum0 += __shfl_xor_sync(0xffffffffu, sum0, 2);
    sum1 += __shfl_xor_sync(0xffffffffu, sum1, 1);
    sum1 += __shfl_xor_sync(0xffffffffu, sum1, 2);
    const float rl0 = 1.0f / sum0, rl1 = 1.0f / sum1;

    const int grow = b * S1C + q0 + wq * 16 + r;
#pragma unroll
    for (int j = 0; j < 8; j++) {
        const int col = h * 64 + j * 8 + 2 * cq;
        float2 v0 = make_float2(o[j][0] * rl0, o[j][1] * rl0);
        float2 v1 = make_float2(o[j][2] * rl1, o[j][3] * rl1);
        *(float2*)&O[(size_t)grow * ND + col] = v0;
        *(float2*)&O[(size_t)(grow + 8) * ND + col] = v1;
    }
}

// ---------------------------------------------------------------------------
// Launch
// ---------------------------------------------------------------------------
extern "C" void kernel_launch(void* const* d_in, const int* in_sizes, int n_in,
                              void* d_out, int out_size)
{
    (void)in_sizes; (void)n_in; (void)out_size;
    const float* x1 = (const float*)d_in[0];
    const float* x2 = (const float*)d_in[1];
    const float* x3 = (const float*)d_in[2];
    const float* Wq = (const float*)d_in[3];
    const float* Wk = (const float*)d_in[4];
    const float* Wv = (const float*)d_in[5];
    const float* Wo = (const float*)d_in[6];
    const float* bo = (const float*)d_in[7];
    float* out = (float*)d_out;

    float *Q, *K, *V;
    cudaGetSymbolAddress((void**)&Q, g_Q);
    cudaGetSymbolAddress((void**)&K, g_K);
    cudaGetSymbolAddress((void**)&V, g_V);

    cudaFuncSetAttribute(qkv_mma, cudaFuncAttributeMaxDynamicSharedMemorySize,
                         G_TOTAL);
    cudaFuncSetAttribute(out_mma, cudaFuncAttributeMaxDynamicSharedMemorySize,
                         G_TOTAL);
    cudaFuncSetAttribute(attn_mma, cudaFuncAttributeMaxDynamicSharedMemorySize,
                         A_TOT_FLOATS * 4);

    prep_w<<<dim3(16, 16, 4), 256>>>(Wq, Wk, Wv, Wo);

    dim3 gQKV(ND / 128, MROWS / 128, 3);   // (4, 64, 3)
    qkv_mma<<<gQKV, 256, G_TOTAL>>>(x1, x2, x3);

    dim3 gA(S1C / 128, BB * NH);           // (16, 32)
    float* Ap;
    cudaGetSymbolAddress((void**)&Ap, g_ATT);
    attn_mma<<<gA, 256, A_TOT_FLOATS * 4>>>(Q, K, V, Ap);

    dim3 gO(ND / 128, MROWS / 128);        // (4, 64)
    out_mma<<<gO, 256, G_TOTAL>>>(bo, out);
}

// round 10
// speedup vs baseline: 3.5975x; 1.1209x over previous
#include <cuda_runtime.h>
#include <cuda_bf16.h>
#include <cstdint>

// Problem constants
#define BB 4
#define S1C 2048
#define S2C 2048
#define NH 8
#define MROWS (BB * S1C)    // 8192
#define ND 512
#define KD 512

// Scratch (device globals — no allocation allowed)
__device__ float g_Q [MROWS * ND];
__device__ float g_K [MROWS * ND];
__device__ float g_V [MROWS * ND];
__device__ float g_ATT[MROWS * ND];
__device__ __nv_bfloat16 g_WTh[4 * (size_t)KD * ND];  // W^T [n][k] hi
__device__ __nv_bfloat16 g_WTl[4 * (size_t)KD * ND];  // W^T [n][k] lo residual

// ---------------------------------------------------------------------------
// helpers
// ---------------------------------------------------------------------------
__device__ __forceinline__ uint32_t smem_u32(const void* p) {
    uint32_t a;
    asm("{ .reg .u64 t; cvta.to.shared.u64 t, %1; cvt.u32.u64 %0, t; }"
        : "=r"(a) : "l"(p));
    return a;
}

__device__ __forceinline__ void cp16(uint32_t dst, const void* src) {
    asm volatile("cp.async.cg.shared.global [%0], [%1], 16;"
                 :: "r"(dst), "l"(src) : "memory");
}
#define CP_COMMIT() asm volatile("cp.async.commit_group;" ::: "memory")
#define CP_WAIT0()  asm volatile("cp.async.wait_group 0;" ::: "memory")
#define CP_WAIT1()  asm volatile("cp.async.wait_group 1;" ::: "memory")

__device__ __forceinline__ float to_tf32(float x) {
    float y;
    asm("cvt.rna.tf32.f32 %0, %1;" : "=f"(y) : "f"(x));
    return y;
}

__device__ __forceinline__ void mma_bf16(float* c, const uint32_t* a, const uint32_t* b) {
    asm volatile(
        "mma.sync.aligned.m16n8k16.row.col.f32.bf16.bf16.f32 "
        "{%0,%1,%2,%3}, {%4,%5,%6,%7}, {%8,%9}, {%0,%1,%2,%3};"
        : "+f"(c[0]), "+f"(c[1]), "+f"(c[2]), "+f"(c[3])
        : "r"(a[0]), "r"(a[1]), "r"(a[2]), "r"(a[3]), "r"(b[0]), "r"(b[1]));
}

__device__ __forceinline__ void mma_tf32(float* c, const uint32_t* a, const uint32_t* b) {
    asm volatile(
        "mma.sync.aligned.m16n8k8.row.col.f32.tf32.tf32.f32 "
        "{%0,%1,%2,%3}, {%4,%5,%6,%7}, {%8,%9}, {%0,%1,%2,%3};"
        : "+f"(c[0]), "+f"(c[1]), "+f"(c[2]), "+f"(c[3])
        : "r"(a[0]), "r"(a[1]), "r"(a[2]), "r"(a[3]), "r"(b[0]), "r"(b[1]));
}

__device__ __forceinline__ uint32_t pack2(__nv_bfloat16 a, __nv_bfloat16 b) {
    return (uint32_t)__bfloat16_as_ushort(a) | ((uint32_t)__bfloat16_as_ushort(b) << 16);
}

__device__ __forceinline__ void split2(float x, float y, uint32_t& hi, uint32_t& lo) {
    __nv_bfloat16 h0 = __float2bfloat16(x), h1 = __float2bfloat16(y);
    hi = pack2(h0, h1);
    lo = pack2(__float2bfloat16(x - __bfloat162float(h0)),
               __float2bfloat16(y - __bfloat162float(h1)));
}

// ---------------------------------------------------------------------------
// prep: W[k][n] (512x512 fp32) -> g_WTh/g_WTl [n][k] bf16 hi/lo
// Wq (z==0) additionally scaled by 1/8 (folds softmax 1/sqrt(64) into Q).
// ---------------------------------------------------------------------------
__global__ __launch_bounds__(256)
void prep_w(const float* __restrict__ Wq, const float* __restrict__ Wk,
            const float* __restrict__ Wv, const float* __restrict__ Wo)
{
    __shared__ float tbuf[32][33];
    const int z = blockIdx.z;
    const float* W = (z == 0) ? Wq : (z == 1) ? Wk : (z == 2) ? Wv : Wo;
    const float scale = (z == 0) ? 0.125f : 1.0f;
    __nv_bfloat16* oh = g_WTh + (size_t)z * KD * ND;
    __nv_bfloat16* ol = g_WTl + (size_t)z * KD * ND;
    const int k0 = blockIdx.x * 32, n0 = blockIdx.y * 32;
    const int lane = threadIdx.x & 31, r = threadIdx.x >> 5;

#pragma unroll
    for (int i = 0; i < 4; i++) {
        const int row = r + i * 8;
        tbuf[row][lane] = W[(size_t)(k0 + row) * ND + n0 + lane];
    }
    __syncthreads();
#pragma unroll
    for (int i = 0; i < 4; i++) {
        const int row = r + i * 8;
        const float x = tbuf[lane][row] * scale;
        const __nv_bfloat16 hb = __float2bfloat16(x);
        oh[(size_t)(n0 + row) * KD + k0 + lane] = hb;
        ol[(size_t)(n0 + row) * KD + k0 + lane] =
            __float2bfloat16(x - __bfloat162float(hb));
    }
}

// ---------------------------------------------------------------------------
// bf16x3 tensor-core GEMM, cp.async double-buffered, 2 CTAs/SM. (R9-passing)
// ---------------------------------------------------------------------------
#define GA_PITCH 40            // floats
#define GB_PITCH 56            // bf16
#define G_A0  0
#define G_A1  20480
#define G_BH0 40960
#define G_BH1 55296
#define G_BL0 69632
#define G_BL1 83968
#define G_TOTAL 98304          // 96 KB -> 2 CTAs/SM

template <bool ROUND_TF32, bool HAS_BIAS>
__device__ __forceinline__
void gemm_body(const float* __restrict__ A, const __nv_bfloat16* __restrict__ Bh,
               const __nv_bfloat16* __restrict__ Bl, const float* __restrict__ bias,
               float* __restrict__ C, int m0, int n0, char* smc)
{
    const uint32_t sb = smem_u32(smc);
    const int tid = threadIdx.x;
    const int lane = tid & 31;
    const int w = tid >> 5;
    const int wm = w & 1, wn = w >> 1;
    const int r = lane >> 2, cq = lane & 3;

    float c[4][4][4];
#pragma unroll
    for (int i = 0; i < 4; i++)
#pragma unroll
        for (int j = 0; j < 4; j++)
#pragma unroll
            for (int x = 0; x < 4; x++) c[i][j][x] = 0.f;

    auto issue = [&](int kt, int buf) {
        const int k0 = kt * 32;
        const uint32_t ab = sb + (buf ? G_A1 : G_A0);
        const uint32_t hb = sb + (buf ? G_BH1 : G_BH0);
        const uint32_t lb = sb + (buf ? G_BL1 : G_BL0);
#pragma unroll
        for (int it = 0; it < 4; it++) {
            const int ch = tid + it * 256;
            const int row = ch >> 3, seg = ch & 7;
            cp16(ab + row * 160 + seg * 16,
                 A + (size_t)(m0 + row) * KD + k0 + seg * 4);
        }
#pragma unroll
        for (int it = 0; it < 2; it++) {
            const int ch = tid + it * 256;
            const int row = ch >> 2, seg = ch & 3;
            cp16(hb + row * 112 + seg * 16,
                 Bh + (size_t)(n0 + row) * KD + k0 + seg * 8);
            cp16(lb + row * 112 + seg * 16,
                 Bl + (size_t)(n0 + row) * KD + k0 + seg * 8);
        }
        CP_COMMIT();
    };

    issue(0, 0);

    for (int kt = 0; kt < 16; kt++) {
        if (kt < 15) { issue(kt + 1, (kt + 1) & 1); CP_WAIT1(); }
        else         { CP_WAIT0(); }
        __syncthreads();

        const int buf = kt & 1;
        const float* As = (const float*)(smc + (buf ? G_A1 : G_A0));
        const __nv_bfloat16* Bhs = (const __nv_bfloat16*)(smc + (buf ? G_BH1 : G_BH0));
        const __nv_bfloat16* Bls = (const __nv_bfloat16*)(smc + (buf ? G_BL1 : G_BL0));

#pragma unroll
        for (int ks = 0; ks < 2; ks++) {
            const int c0 = ks * 16 + 2 * cq;
            uint32_t ah[4][4], al[4][4];
#pragma unroll
            for (int i = 0; i < 4; i++) {
                const int row0 = wm * 64 + i * 16 + r;
                float2 v0 = *(const float2*)&As[row0 * GA_PITCH + c0];
                float2 v1 = *(const float2*)&As[(row0 + 8) * GA_PITCH + c0];
                float2 v2 = *(const float2*)&As[row0 * GA_PITCH + c0 + 8];
                float2 v3 = *(const float2*)&As[(row0 + 8) * GA_PITCH + c0 + 8];
                split2(v0.x, v0.y, ah[i][0], al[i][0]);
                split2(v1.x, v1.y, ah[i][1], al[i][1]);
                split2(v2.x, v2.y, ah[i][2], al[i][2]);
                split2(v3.x, v3.y, ah[i][3], al[i][3]);
            }
#pragma unroll
            for (int j = 0; j < 4; j++) {
                const int n = wn * 32 + j * 8 + r;
                const int kb = ks * 16 + 2 * cq;
                uint32_t bh2[2] = { *(const uint32_t*)&Bhs[n * GB_PITCH + kb],
                                    *(const uint32_t*)&Bhs[n * GB_PITCH + kb + 8] };
                uint32_t bl2[2] = { *(const uint32_t*)&Bls[n * GB_PITCH + kb],
                                    *(const uint32_t*)&Bls[n * GB_PITCH + kb + 8] };
#pragma unroll
                for (int i = 0; i < 4; i++) {
                    mma_bf16(c[i][j], ah[i], bh2);
                    mma_bf16(c[i][j], ah[i], bl2);
                    mma_bf16(c[i][j], al[i], bh2);
                }
            }
        }
        __syncthreads();
    }

#pragma unroll
    for (int i = 0; i < 4; i++) {
        const int row = m0 + wm * 64 + i * 16 + r;
#pragma unroll
        for (int j = 0; j < 4; j++) {
            const int col = n0 + wn * 32 + j * 8 + 2 * cq;
            float2 v0 = make_float2(c[i][j][0], c[i][j][1]);
            float2 v1 = make_float2(c[i][j][2], c[i][j][3]);
            if (HAS_BIAS) {
                const float2 bz = *(const float2*)&bias[col];
                v0.x += bz.x; v0.y += bz.y;
                v1.x += bz.x; v1.y += bz.y;
            }
            if (ROUND_TF32) {
                v0.x = to_tf32(v0.x); v0.y = to_tf32(v0.y);
                v1.x = to_tf32(v1.x); v1.y = to_tf32(v1.y);
            }
            *(float2*)&C[(size_t)row * ND + col] = v0;
            *(float2*)&C[(size_t)(row + 8) * ND + col] = v1;
        }
    }
}

__global__ __launch_bounds__(256, 2)
void qkv_mma(const float* __restrict__ x1, const float* __restrict__ x2,
             const float* __restrict__ x3)
{
    extern __shared__ char smc[];
    const int z = blockIdx.z;
    const float* A = (z == 0) ? x1 : (z == 1) ? x2 : x3;
    float* C = (z == 0) ? g_Q : (z == 1) ? g_K : g_V;
    const __nv_bfloat16* Bh = g_WTh + (size_t)z * KD * ND;
    const __nv_bfloat16* Bl = g_WTl + (size_t)z * KD * ND;
    gemm_body<true, false>(A, Bh, Bl, nullptr, C,
                           blockIdx.y * 128, blockIdx.x * 128, smc);
}

__global__ __launch_bounds__(256, 2)
void out_mma(const float* __restrict__ bias, float* __restrict__ C)
{
    extern __shared__ char smc[];
    const __nv_bfloat16* Bh = g_WTh + (size_t)3 * KD * ND;
    const __nv_bfloat16* Bl = g_WTl + (size_t)3 * KD * ND;
    gemm_body<false, true>(g_ATT, Bh, Bl, bias, C,
                           blockIdx.y * 128, blockIdx.x * 128, smc);
}

// ---------------------------------------------------------------------------
// Flash attention with k-slot relabeling q=[0,2,4,6,1,3,5,7]:
//  - QK: K fragment = one LDS.64 (adjacent cols 2cq,2cq+1); Q hoisted likewise.
//  - PV: S accumulator c-layout IS the A fragment (pa = s[0],s[2],s[1],s[3]);
//    P never touches smem. V rows 2cq/2cq+1, pitch 68 (bank-clean).
// Staggered cp.async: V(t) under QK(t), K(t+1) under PV(t).
// ---------------------------------------------------------------------------
#define AQ_PITCH 68
#define AK_PITCH 72
#define AV_PITCH 68
#define A_QS 0
#define A_KS 8704                     // 128*68
#define A_VS (8704 + 4608)            // + 64*72
#define A_TOT_FLOATS (A_VS + 4352)    // + 64*68 = 17664 floats = 70656 B

__global__ __launch_bounds__(256, 2)
void attn_mma(const float* __restrict__ Q, const float* __restrict__ K,
              const float* __restrict__ V, float* __restrict__ O)
{
    extern __shared__ float sm[];
    const uint32_t sb = smem_u32(sm);
    float* Qs = sm + A_QS;
    float* Ks = sm + A_KS;
    float* Vs = sm + A_VS;

    const int tid = threadIdx.x;
    const int lane = tid & 31;
    const int wq = tid >> 5;
    const int r = lane >> 2, cq = lane & 3;

    const int bh = blockIdx.y;
    const int b = bh >> 3, h = bh & 7;
    const int q0 = blockIdx.x * 128;

    const float* Qb = Q + (size_t)(b * S1C + q0) * ND + h * 64;
    const float* Kb = K + (size_t)(b * S2C) * ND + h * 64;
    const float* Vb = V + (size_t)(b * S2C) * ND + h * 64;

    auto issueK = [&](int kt) {
#pragma unroll
        for (int it = 0; it < 4; it++) {
            const int ch = tid + it * 256;
            const int row = ch >> 4, seg = ch & 15;
            cp16(sb + A_KS * 4 + row * (AK_PITCH * 4) + seg * 16,
                 Kb + (size_t)(kt * 64 + row) * ND + seg * 4);
        }
        CP_COMMIT();
    };
    auto issueV = [&](int kt) {
#pragma unroll
        for (int it = 0; it < 4; it++) {
            const int ch = tid + it * 256;
            const int row = ch >> 4, seg = ch & 15;
            cp16(sb + A_VS * 4 + row * (AV_PITCH * 4) + seg * 16,
                 Vb + (size_t)(kt * 64 + row) * ND + seg * 4);
        }
        CP_COMMIT();
    };

    // stage Q via cp.async (already scaled + tf32-rounded)
#pragma unroll
    for (int it = 0; it < 8; it++) {
        const int ch = tid + it * 256;
        const int row = ch >> 4, seg = ch & 15;
        cp16(sb + A_QS * 4 + row * (AQ_PITCH * 4) + seg * 16,
             Qb + (size_t)row * ND + seg * 4);
    }
    CP_COMMIT();
    issueK(0);

    // wait for Q (+K0), hoist Q fragments (relabeled: cols 2cq,2cq+1)
    CP_WAIT0();
    __syncthreads();
    const int prow0 = wq * 16 + r;
    uint32_t qa[8][4];
#pragma unroll
    for (int kf = 0; kf < 8; kf++) {
        const int col = kf * 8 + 2 * cq;
        float2 lo = *(const float2*)&Qs[prow0 * AQ_PITCH + col];
        float2 hi = *(const float2*)&Qs[(prow0 + 8) * AQ_PITCH + col];
        qa[kf][0] = __float_as_uint(lo.x);   // k-slot cq
        qa[kf][1] = __float_as_uint(hi.x);
        qa[kf][2] = __float_as_uint(lo.y);   // k-slot cq+4
        qa[kf][3] = __float_as_uint(hi.y);
    }

    float o[8][4];
#pragma unroll
    for (int j = 0; j < 8; j++)
#pragma unroll
        for (int x = 0; x < 4; x++) o[j][x] = 0.f;
    float sum0 = 0.f, sum1 = 0.f;

    for (int kt = 0; kt < S2C / 64; kt++) {
        CP_WAIT0();          // K(t) complete
        __syncthreads();     // visible; PV(t-1) reads of Vs done

        issueV(kt);          // overlaps QK(t)

        float s8[8][4];
#pragma unroll
        for (int j = 0; j < 8; j++)
#pragma unroll
            for (int x = 0; x < 4; x++) s8[j][x] = 0.f;

        // S = Q @ K^T (K fragment = single LDS.64, relabeled)
#pragma unroll
        for (int kf = 0; kf < 8; kf++) {
            const int col = kf * 8 + 2 * cq;
#pragma unroll
            for (int j = 0; j < 8; j++) {
                float2 kv = *(const float2*)&Ks[(j * 8 + r) * AK_PITCH + col];
                uint32_t kb2[2] = { __float_as_uint(kv.x),    // k-slot cq
                                    __float_as_uint(kv.y) };  // k-slot cq+4
                mma_tf32(s8[j], qa[kf], kb2);
            }
        }

        // unshifted softmax partials
#pragma unroll
        for (int j = 0; j < 8; j++) {
            s8[j][0] = __expf(s8[j][0]);
            s8[j][1] = __expf(s8[j][1]);
            s8[j][2] = __expf(s8[j][2]);
            s8[j][3] = __expf(s8[j][3]);
            sum0 += s8[j][0] + s8[j][1];
            sum1 += s8[j][2] + s8[j][3];
        }

        CP_WAIT0();          // V(t) complete
        __syncthreads();     // visible; QK(t) reads of Ks done

        if (kt < S2C / 64 - 1) issueK(kt + 1);   // overlaps PV(t)

        // O += P @ V : P fragment directly from S accumulator (no smem)
#pragma unroll
        for (int jk = 0; jk < 8; jk++) {         // key block
            uint32_t pa[4];
            pa[0] = __float_as_uint(to_tf32(s8[jk][0]));  // (row r,  key 2cq)
            pa[1] = __float_as_uint(to_tf32(s8[jk][2]));  // (row r+8,key 2cq)
            pa[2] = __float_as_uint(to_tf32(s8[jk][1]));  // (row r,  key 2cq+1)
            pa[3] = __float_as_uint(to_tf32(s8[jk][3]));  // (row r+8,key 2cq+1)
#pragma unroll
            for (int jd = 0; jd < 8; jd++) {     // dim block
                const int vcol = jd * 8 + r;
                uint32_t vb2[2] = {
                    __float_as_uint(Vs[(jk * 8 + 2 * cq) * AV_PITCH + vcol]),
                    __float_as_uint(Vs[(jk * 8 + 2 * cq + 1) * AV_PITCH + vcol]) };
                mma_tf32(o[jd], pa, vb2);
            }
        }
    }

    sum0 += __shfl_xor_sync(0xffffffffu, sum0, 1);
    sum0 += __shfl_xor_sync(0xffffffffu, sum0, 2);
    sum1 += __shfl_xor_sync(0xffffffffu, sum1, 1);
    sum1 += __shfl_xor_sync(0xffffffffu, sum1, 2);
    const float rl0 = 1.0f / sum0, rl1 = 1.0f / sum1;

    const int grow = b * S1C + q0 + wq * 16 + r;
#pragma unroll
    for (int j = 0; j < 8; j++) {
        const int col = h * 64 + j * 8 + 2 * cq;
        float2 v0 = make_float2(o[j][0] * rl0, o[j][1] * rl0);
        float2 v1 = make_float2(o[j][2] * rl1, o[j][3] * rl1);
        *(float2*)&O[(size_t)grow * ND + col] = v0;
        *(float2*)&O[(size_t)(grow + 8) * ND + col] = v1;
    }
}

// ---------------------------------------------------------------------------
// Launch
// ---------------------------------------------------------------------------
extern "C" void kernel_launch(void* const* d_in, const int* in_sizes, int n_in,
                              void* d_out, int out_size)
{
    (void)in_sizes; (void)n_in; (void)out_size;
    const float* x1 = (const float*)d_in[0];
    const float* x2 = (const float*)d_in[1];
    const float* x3 = (const float*)d_in[2];
    const float* Wq = (const float*)d_in[3];
    const float* Wk = (const float*)d_in[4];
    const float* Wv = (const float*)d_in[5];
    const float* Wo = (const float*)d_in[6];
    const float* bo = (const float*)d_in[7];
    float* out = (float*)d_out;

    float *Q, *K, *V, *Ap;
    cudaGetSymbolAddress((void**)&Q, g_Q);
    cudaGetSymbolAddress((void**)&K, g_K);
    cudaGetSymbolAddress((void**)&V, g_V);
    cudaGetSymbolAddress((void**)&Ap, g_ATT);

    cudaFuncSetAttribute(qkv_mma, cudaFuncAttributeMaxDynamicSharedMemorySize,
                         G_TOTAL);
    cudaFuncSetAttribute(out_mma, cudaFuncAttributeMaxDynamicSharedMemorySize,
                         G_TOTAL);
    cudaFuncSetAttribute(attn_mma, cudaFuncAttributeMaxDynamicSharedMemorySize,
                         A_TOT_FLOATS * 4);

    prep_w<<<dim3(16, 16, 4), 256>>>(Wq, Wk, Wv, Wo);

    dim3 gQKV(ND / 128, MROWS / 128, 3);   // (4, 64, 3)
    qkv_mma<<<gQKV, 256, G_TOTAL>>>(x1, x2, x3);

    dim3 gA(S1C / 128, BB * NH);           // (16, 32)
    attn_mma<<<gA, 256, A_TOT_FLOATS * 4>>>(Q, K, V, Ap);

    dim3 gO(ND / 128, MROWS / 128);        // (4, 64)
    out_mma<<<gO, 256, G_TOTAL>>>(bo, out);
}

// round 11
// speedup vs baseline: 3.8478x; 1.0696x over previous
#include <cuda_runtime.h>
#include <cuda_bf16.h>
#include <cstdint>

// Problem constants
#define BB 4
#define S1C 2048
#define S2C 2048
#define NH 8
#define MROWS (BB * S1C)    // 8192
#define ND 512
#define KD 512

// Scratch (device globals — no allocation allowed)
__device__ __align__(16) float g_Q [MROWS * ND];
__device__ __align__(16) float g_K [MROWS * ND];
__device__ __align__(16) float g_V [MROWS * ND];   // holds V^T: [B*512+col][2048]
__device__ __align__(16) __nv_bfloat16 g_Xh[3 * (size_t)MROWS * ND];
__device__ __align__(16) __nv_bfloat16 g_Xl[3 * (size_t)MROWS * ND];
__device__ __align__(16) __nv_bfloat16 g_ATTh[(size_t)MROWS * ND];
__device__ __align__(16) __nv_bfloat16 g_ATTl[(size_t)MROWS * ND];
__device__ __align__(16) __nv_bfloat16 g_WTh[4 * (size_t)KD * ND];  // W^T [n][k] hi
__device__ __align__(16) __nv_bfloat16 g_WTl[4 * (size_t)KD * ND];  // W^T [n][k] lo

// ---------------------------------------------------------------------------
// helpers
// ---------------------------------------------------------------------------
__device__ __forceinline__ uint32_t smem_u32(const void* p) {
    uint32_t a;
    asm("{ .reg .u64 t; cvta.to.shared.u64 t, %1; cvt.u32.u64 %0, t; }"
        : "=r"(a) : "l"(p));
    return a;
}

__device__ __forceinline__ void cp16(uint32_t dst, const void* src) {
    asm volatile("cp.async.cg.shared.global [%0], [%1], 16;"
                 :: "r"(dst), "l"(src) : "memory");
}
#define CP_COMMIT() asm volatile("cp.async.commit_group;" ::: "memory")
#define CP_WAIT0()  asm volatile("cp.async.wait_group 0;" ::: "memory")
#define CP_WAIT1()  asm volatile("cp.async.wait_group 1;" ::: "memory")

__device__ __forceinline__ float to_tf32(float x) {
    float y;
    asm("cvt.rna.tf32.f32 %0, %1;" : "=f"(y) : "f"(x));
    return y;
}

__device__ __forceinline__ void mma_bf16(float* c, const uint32_t* a, const uint32_t* b) {
    asm volatile(
        "mma.sync.aligned.m16n8k16.row.col.f32.bf16.bf16.f32 "
        "{%0,%1,%2,%3}, {%4,%5,%6,%7}, {%8,%9}, {%0,%1,%2,%3};"
        : "+f"(c[0]), "+f"(c[1]), "+f"(c[2]), "+f"(c[3])
        : "r"(a[0]), "r"(a[1]), "r"(a[2]), "r"(a[3]), "r"(b[0]), "r"(b[1]));
}

__device__ __forceinline__ void mma_tf32(float* c, const uint32_t* a, const uint32_t* b) {
    asm volatile(
        "mma.sync.aligned.m16n8k8.row.col.f32.tf32.tf32.f32 "
        "{%0,%1,%2,%3}, {%4,%5,%6,%7}, {%8,%9}, {%0,%1,%2,%3};"
        : "+f"(c[0]), "+f"(c[1]), "+f"(c[2]), "+f"(c[3])
        : "r"(a[0]), "r"(a[1]), "r"(a[2]), "r"(a[3]), "r"(b[0]), "r"(b[1]));
}

__device__ __forceinline__ uint32_t pack2(__nv_bfloat16 a, __nv_bfloat16 b) {
    return (uint32_t)__bfloat16_as_ushort(a) | ((uint32_t)__bfloat16_as_ushort(b) << 16);
}

__device__ __forceinline__ void split2(float x, float y, uint32_t& hi, uint32_t& lo) {
    __nv_bfloat16 h0 = __float2bfloat16(x), h1 = __float2bfloat16(y);
    hi = pack2(h0, h1);
    lo = pack2(__float2bfloat16(x - __bfloat162float(h0)),
               __float2bfloat16(y - __bfloat162float(h1)));
}

// ---------------------------------------------------------------------------
// prep_w: W[k][n] -> W^T [n][k] bf16 hi/lo (Wq scaled by 1/8)
// ---------------------------------------------------------------------------
__global__ __launch_bounds__(256)
void prep_w(const float* __restrict__ Wq, const float* __restrict__ Wk,
            const float* __restrict__ Wv, const float* __restrict__ Wo)
{
    __shared__ float tbuf[32][33];
    const int z = blockIdx.z;
    const float* W = (z == 0) ? Wq : (z == 1) ? Wk : (z == 2) ? Wv : Wo;
    const float scale = (z == 0) ? 0.125f : 1.0f;
    __nv_bfloat16* oh = g_WTh + (size_t)z * KD * ND;
    __nv_bfloat16* ol = g_WTl + (size_t)z * KD * ND;
    const int k0 = blockIdx.x * 32, n0 = blockIdx.y * 32;
    const int lane = threadIdx.x & 31, r = threadIdx.x >> 5;

#pragma unroll
    for (int i = 0; i < 4; i++) {
        const int row = r + i * 8;
        tbuf[row][lane] = W[(size_t)(k0 + row) * ND + n0 + lane];
    }
    __syncthreads();
#pragma unroll
    for (int i = 0; i < 4; i++) {
        const int row = r + i * 8;
        const float x = tbuf[lane][row] * scale;
        const __nv_bfloat16 hb = __float2bfloat16(x);
        oh[(size_t)(n0 + row) * KD + k0 + lane] = hb;
        ol[(size_t)(n0 + row) * KD + k0 + lane] =
            __float2bfloat16(x - __bfloat162float(hb));
    }
}

// ---------------------------------------------------------------------------
// prep_x: split x (fp32) -> bf16 hi/lo, same [m][k] layout. grid (2048, 3).
// ---------------------------------------------------------------------------
__global__ __launch_bounds__(256)
void prep_x(const float* __restrict__ x1, const float* __restrict__ x2,
            const float* __restrict__ x3)
{
    const int z = blockIdx.y;
    const float* x = (z == 0) ? x1 : (z == 1) ? x2 : x3;
    __nv_bfloat16* oh = g_Xh + (size_t)z * MROWS * ND;
    __nv_bfloat16* ol = g_Xl + (size_t)z * MROWS * ND;
    const size_t idx = ((size_t)blockIdx.x * 256 + threadIdx.x) * 8;
    float4 v0 = *(const float4*)&x[idx];
    float4 v1 = *(const float4*)&x[idx + 4];
    uint32_t h[4], l[4];
    split2(v0.x, v0.y, h[0], l[0]);
    split2(v0.z, v0.w, h[1], l[1]);
    split2(v1.x, v1.y, h[2], l[2]);
    split2(v1.z, v1.w, h[3], l[3]);
    *(uint4*)&oh[idx] = make_uint4(h[0], h[1], h[2], h[3]);
    *(uint4*)&ol[idx] = make_uint4(l[0], l[1], l[2], l[3]);
}

// ---------------------------------------------------------------------------
// bf16x3 GEMM, all operands pre-split bf16, cp.async double-buffered.
// A/B smem pitch = 40 bf16 (80B) — conflict-free (bank = 20*row + cq pattern).
// Loop body: fragment LDS + HMMA only.
// ---------------------------------------------------------------------------
#define GP 40                  // bf16 pitch
#define G_ARR 10240            // 128*80 bytes per array per buffer
#define G_BUF 40960            // 4 arrays
#define G_TOTAL 81920          // 80 KB -> 2 CTAs/SM

template <bool ROUND_TF32, bool HAS_BIAS>
__device__ __forceinline__
void gemm_body(const __nv_bfloat16* __restrict__ Ah, const __nv_bfloat16* __restrict__ Al,
               const __nv_bfloat16* __restrict__ Bh, const __nv_bfloat16* __restrict__ Bl,
               const float* __restrict__ bias, float* __restrict__ C,
               int m0, int n0, char* smc, bool write_vt)
{
    const uint32_t sb = smem_u32(smc);
    const int tid = threadIdx.x;
    const int lane = tid & 31;
    const int w = tid >> 5;
    const int wm = w & 1, wn = w >> 1;
    const int r = lane >> 2, cq = lane & 3;

    float c[4][4][4];
#pragma unroll
    for (int i = 0; i < 4; i++)
#pragma unroll
        for (int j = 0; j < 4; j++)
#pragma unroll
            for (int x = 0; x < 4; x++) c[i][j][x] = 0.f;

    // stage one k-tile: 4 arrays x 512 chunks of 16B (2 chunks/thread/array)
    auto issue = [&](int kt, int buf) {
        const int k0 = kt * 32;
        const uint32_t base = sb + (buf ? G_BUF : 0);
#pragma unroll
        for (int it = 0; it < 2; it++) {
            const int ch = tid + it * 256;          // 0..511
            const int row = ch >> 2, seg = ch & 3;  // row 0..127, 16B seg
            const uint32_t off = row * 80 + seg * 16;
            const size_t ga = (size_t)(m0 + row) * KD + k0 + seg * 8;
            const size_t gb = (size_t)(n0 + row) * KD + k0 + seg * 8;
            cp16(base + off,             Ah + ga);
            cp16(base + G_ARR + off,     Al + ga);
            cp16(base + 2 * G_ARR + off, Bh + gb);
            cp16(base + 3 * G_ARR + off, Bl + gb);
        }
        CP_COMMIT();
    };

    issue(0, 0);

    for (int kt = 0; kt < 16; kt++) {
        if (kt < 15) { issue(kt + 1, (kt + 1) & 1); CP_WAIT1(); }
        else         { CP_WAIT0(); }
        __syncthreads();

        const char* bufp = smc + ((kt & 1) ? G_BUF : 0);
        const __nv_bfloat16* Ahs = (const __nv_bfloat16*)(bufp);
        const __nv_bfloat16* Als = (const __nv_bfloat16*)(bufp + G_ARR);
        const __nv_bfloat16* Bhs = (const __nv_bfloat16*)(bufp + 2 * G_ARR);
        const __nv_bfloat16* Bls = (const __nv_bfloat16*)(bufp + 3 * G_ARR);

#pragma unroll
        for (int ks = 0; ks < 2; ks++) {
            const int kb = ks * 16 + 2 * cq;        // element col of fragment
            uint32_t ah[4][4], al[4][4];
#pragma unroll
            for (int i = 0; i < 4; i++) {
                const int row = wm * 64 + i * 16 + r;
                ah[i][0] = *(const uint32_t*)&Ahs[row * GP + kb];
                ah[i][1] = *(const uint32_t*)&Ahs[(row + 8) * GP + kb];
                ah[i][2] = *(const uint32_t*)&Ahs[row * GP + kb + 8];
                ah[i][3] = *(const uint32_t*)&Ahs[(row + 8) * GP + kb + 8];
                al[i][0] = *(const uint32_t*)&Als[row * GP + kb];
                al[i][1] = *(const uint32_t*)&Als[(row + 8) * GP + kb];
                al[i][2] = *(const uint32_t*)&Als[row * GP + kb + 8];
                al[i][3] = *(const uint32_t*)&Als[(row + 8) * GP + kb + 8];
            }
#pragma unroll
            for (int j = 0; j < 4; j++) {
                const int n = wn * 32 + j * 8 + r;
                uint32_t bh2[2] = { *(const uint32_t*)&Bhs[n * GP + kb],
                                    *(const uint32_t*)&Bhs[n * GP + kb + 8] };
                uint32_t bl2[2] = { *(const uint32_t*)&Bls[n * GP + kb],
                                    *(const uint32_t*)&Bls[n * GP + kb + 8] };
#pragma unroll
                for (int i = 0; i < 4; i++) {
                    mma_bf16(c[i][j], ah[i], bh2);
                    mma_bf16(c[i][j], ah[i], bl2);
                    mma_bf16(c[i][j], al[i], bh2);
                }
            }
        }
        __syncthreads();
    }

    // epilogue
#pragma unroll
    for (int i = 0; i < 4; i++) {
        const int row = m0 + wm * 64 + i * 16 + r;
#pragma unroll
        for (int j = 0; j < 4; j++) {
            const int col = n0 + wn * 32 + j * 8 + 2 * cq;
            float2 v0 = make_float2(c[i][j][0], c[i][j][1]);
            float2 v1 = make_float2(c[i][j][2], c[i][j][3]);
            if (HAS_BIAS) {
                const float2 bz = *(const float2*)&bias[col];
                v0.x += bz.x; v0.y += bz.y;
                v1.x += bz.x; v1.y += bz.y;
            }
            if (ROUND_TF32) {
                v0.x = to_tf32(v0.x); v0.y = to_tf32(v0.y);
                v1.x = to_tf32(v1.x); v1.y = to_tf32(v1.y);
            }
            if (write_vt) {
                // V^T: C[(b*512 + col)][seq], b = row>>11, seq = row&2047
                const size_t b0 = ((size_t)(row >> 11) * 512 + col) * 2048;
                const int sq0 = row & 2047;
                C[b0 + sq0]            = v0.x;
                C[b0 + 2048 + sq0]     = v0.y;
                C[b0 + sq0 + 8]        = v1.x;
                C[b0 + 2048 + sq0 + 8] = v1.y;
            } else {
                *(float2*)&C[(size_t)row * ND + col] = v0;
                *(float2*)&C[(size_t)(row + 8) * ND + col] = v1;
            }
        }
    }
}

__global__ __launch_bounds__(256, 2)
void qkv_mma()
{
    extern __shared__ char smc[];
    const int z = blockIdx.z;
    const __nv_bfloat16* Ah = g_Xh + (size_t)z * MROWS * ND;
    const __nv_bfloat16* Al = g_Xl + (size_t)z * MROWS * ND;
    const __nv_bfloat16* Bh = g_WTh + (size_t)z * KD * ND;
    const __nv_bfloat16* Bl = g_WTl + (size_t)z * KD * ND;
    float* C = (z == 0) ? g_Q : (z == 1) ? g_K : g_V;
    gemm_body<true, false>(Ah, Al, Bh, Bl, nullptr, C,
                           blockIdx.y * 128, blockIdx.x * 128, smc, z == 2);
}

__global__ __launch_bounds__(256, 2)
void out_mma(const float* __restrict__ bias, float* __restrict__ C)
{
    extern __shared__ char smc[];
    gemm_body<false, true>(g_ATTh, g_ATTl,
                           g_WTh + (size_t)3 * KD * ND, g_WTl + (size_t)3 * KD * ND,
                           bias, C, blockIdx.y * 128, blockIdx.x * 128, smc, false);
}

// ---------------------------------------------------------------------------
// Flash attention. K [key][dim] pitch 72 (LDS.64 frags); V^T staged [dim][key]
// pitch 72 (LDS.64 frags). P stays in registers. Output written as bf16 hi/lo.
// ---------------------------------------------------------------------------
#define AQ_PITCH 68
#define AK_PITCH 72
#define AVT_PITCH 72
#define A_QS 0
#define A_KS 8704                     // 128*68
#define A_VS (8704 + 4608)            // + 64*72
#define A_TOT_FLOATS (A_VS + 4608)    // + 64*72 = 17920 floats = 71680 B

__global__ __launch_bounds__(256, 2)
void attn_mma(const float* __restrict__ Q, const float* __restrict__ K,
              const float* __restrict__ VT)
{
    extern __shared__ float sm[];
    const uint32_t sb = smem_u32(sm);
    float* Qs = sm + A_QS;
    float* Ks = sm + A_KS;
    float* Vt = sm + A_VS;

    const int tid = threadIdx.x;
    const int lane = tid & 31;
    const int wq = tid >> 5;
    const int r = lane >> 2, cq = lane & 3;

    const int bh = blockIdx.y;
    const int b = bh >> 3, h = bh & 7;
    const int q0 = blockIdx.x * 128;

    const float* Qb = Q + (size_t)(b * S1C + q0) * ND + h * 64;
    const float* Kb = K + (size_t)(b * S2C) * ND + h * 64;
    const float* VbT = VT + ((size_t)b * 512 + h * 64) * 2048;   // [64 dims][2048 seq]

    auto issueK = [&](int kt) {
#pragma unroll
        for (int it = 0; it < 4; it++) {
            const int ch = tid + it * 256;
            const int row = ch >> 4, seg = ch & 15;      // key row, 16B seg
            cp16(sb + A_KS * 4 + row * (AK_PITCH * 4) + seg * 16,
                 Kb + (size_t)(kt * 64 + row) * ND + seg * 4);
        }
        CP_COMMIT();
    };
    auto issueV = [&](int kt) {
#pragma unroll
        for (int it = 0; it < 4; it++) {
            const int ch = tid + it * 256;
            const int row = ch >> 4, seg = ch & 15;      // dim row, 16B seg over keys
            cp16(sb + A_VS * 4 + row * (AVT_PITCH * 4) + seg * 16,
                 VbT + (size_t)row * 2048 + kt * 64 + seg * 4);
        }
        CP_COMMIT();
    };

    // stage Q (already scaled + tf32-rounded)
#pragma unroll
    for (int it = 0; it < 8; it++) {
        const int ch = tid + it * 256;
        const int row = ch >> 4, seg = ch & 15;
        cp16(sb + A_QS * 4 + row * (AQ_PITCH * 4) + seg * 16,
             Qb + (size_t)row * ND + seg * 4);
    }
    CP_COMMIT();
    issueK(0);

    CP_WAIT0();
    __syncthreads();
    const int prow0 = wq * 16 + r;
    uint32_t qa[8][4];
#pragma unroll
    for (int kf = 0; kf < 8; kf++) {
        const int col = kf * 8 + 2 * cq;
        float2 lo = *(const float2*)&Qs[prow0 * AQ_PITCH + col];
        float2 hi = *(const float2*)&Qs[(prow0 + 8) * AQ_PITCH + col];
        qa[kf][0] = __float_as_uint(lo.x);
        qa[kf][1] = __float_as_uint(hi.x);
        qa[kf][2] = __float_as_uint(lo.y);
        qa[kf][3] = __float_as_uint(hi.y);
    }

    float o[8][4];
#pragma unroll
    for (int j = 0; j < 8; j++)
#pragma unroll
        for (int x = 0; x < 4; x++) o[j][x] = 0.f;
    float sum0 = 0.f, sum1 = 0.f;

    for (int kt = 0; kt < S2C / 64; kt++) {
        CP_WAIT0();
        __syncthreads();

        issueV(kt);          // overlaps QK(t)

        float s8[8][4];
#pragma unroll
        for (int j = 0; j < 8; j++)
#pragma unroll
            for (int x = 0; x < 4; x++) s8[j][x] = 0.f;

#pragma unroll
        for (int kf = 0; kf < 8; kf++) {
            const int col = kf * 8 + 2 * cq;
#pragma unroll
            for (int j = 0; j < 8; j++) {
                float2 kv = *(const float2*)&Ks[(j * 8 + r) * AK_PITCH + col];
                uint32_t kb2[2] = { __float_as_uint(kv.x),
                                    __float_as_uint(kv.y) };
                mma_tf32(s8[j], qa[kf], kb2);
            }
        }

#pragma unroll
        for (int j = 0; j < 8; j++) {
            s8[j][0] = __expf(s8[j][0]);
            s8[j][1] = __expf(s8[j][1]);
            s8[j][2] = __expf(s8[j][2]);
            s8[j][3] = __expf(s8[j][3]);
            sum0 += s8[j][0] + s8[j][1];
            sum1 += s8[j][2] + s8[j][3];
        }

        CP_WAIT0();          // V(t) complete
        __syncthreads();

        if (kt < S2C / 64 - 1) issueK(kt + 1);   // overlaps PV(t)

        // O += P @ V : P from S accumulator; V fragment = one LDS.64
#pragma unroll
        for (int jk = 0; jk < 8; jk++) {
            uint32_t pa[4];
            pa[0] = __float_as_uint(to_tf32(s8[jk][0]));
            pa[1] = __float_as_uint(to_tf32(s8[jk][2]));
            pa[2] = __float_as_uint(to_tf32(s8[jk][1]));
            pa[3] = __float_as_uint(to_tf32(s8[jk][3]));
#pragma unroll
            for (int jd = 0; jd < 8; jd++) {
                float2 vv = *(const float2*)&Vt[(jd * 8 + r) * AVT_PITCH + jk * 8 + 2 * cq];
                uint32_t vb2[2] = { __float_as_uint(vv.x),
                                    __float_as_uint(vv.y) };
                mma_tf32(o[jd], pa, vb2);
            }
        }
    }

    sum0 += __shfl_xor_sync(0xffffffffu, sum0, 1);
    sum0 += __shfl_xor_sync(0xffffffffu, sum0, 2);
    sum1 += __shfl_xor_sync(0xffffffffu, sum1, 1);
    sum1 += __shfl_xor_sync(0xffffffffu, sum1, 2);
    const float rl0 = 1.0f / sum0, rl1 = 1.0f / sum1;

    // write output as bf16 hi/lo (feeds out_mma directly)
    const int grow = b * S1C + q0 + wq * 16 + r;
#pragma unroll
    for (int j = 0; j < 8; j++) {
        const int col = h * 64 + j * 8 + 2 * cq;
        uint32_t h0, l0, h1, l1;
        split2(o[j][0] * rl0, o[j][1] * rl0, h0, l0);
        split2(o[j][2] * rl1, o[j][3] * rl1, h1, l1);
        *(uint32_t*)&g_ATTh[(size_t)grow * ND + col] = h0;
        *(uint32_t*)&g_ATTl[(size_t)grow * ND + col] = l0;
        *(uint32_t*)&g_ATTh[(size_t)(grow + 8) * ND + col] = h1;
        *(uint32_t*)&g_ATTl[(size_t)(grow + 8) * ND + col] = l1;
    }
}

// ---------------------------------------------------------------------------
// Launch
// ---------------------------------------------------------------------------
extern "C" void kernel_launch(void* const* d_in, const int* in_sizes, int n_in,
                              void* d_out, int out_size)
{
    (void)in_sizes; (void)n_in; (void)out_size;
    const float* x1 = (const float*)d_in[0];
    const float* x2 = (const float*)d_in[1];
    const float* x3 = (const float*)d_in[2];
    const float* Wq = (const float*)d_in[3];
    const float* Wk = (const float*)d_in[4];
    const float* Wv = (const float*)d_in[5];
    const float* Wo = (const float*)d_in[6];
    const float* bo = (const float*)d_in[7];
    float* out = (float*)d_out;

    float *Q, *K, *V;
    cudaGetSymbolAddress((void**)&Q, g_Q);
    cudaGetSymbolAddress((void**)&K, g_K);
    cudaGetSymbolAddress((void**)&V, g_V);

    cudaFuncSetAttribute(qkv_mma, cudaFuncAttributeMaxDynamicSharedMemorySize,
                         G_TOTAL);
    cudaFuncSetAttribute(out_mma, cudaFuncAttributeMaxDynamicSharedMemorySize,
                         G_TOTAL);
    cudaFuncSetAttribute(attn_mma, cudaFuncAttributeMaxDynamicSharedMemorySize,
                         A_TOT_FLOATS * 4);

    prep_w<<<dim3(16, 16, 4), 256>>>(Wq, Wk, Wv, Wo);
    prep_x<<<dim3(MROWS * ND / 2048, 3), 256>>>(x1, x2, x3);

    dim3 gQKV(ND / 128, MROWS / 128, 3);   // (4, 64, 3)
    qkv_mma<<<gQKV, 256, G_TOTAL>>>();

    dim3 gA(S1C / 128, BB * NH);           // (16, 32)
    attn_mma<<<gA, 256, A_TOT_FLOATS * 4>>>(Q, K, V);

    dim3 gO(ND / 128, MROWS / 128);        // (4, 64)
    out_mma<<<gO, 256, G_TOTAL>>>(bo, out);
}

// round 12
// speedup vs baseline: 4.0284x; 1.0469x over previous
#include <cuda_runtime.h>
#include <cuda_bf16.h>
#include <cstdint>

// Problem constants
#define BB 4
#define S1C 2048
#define S2C 2048
#define NH 8
#define MROWS (BB * S1C)    // 8192
#define ND 512
#define KD 512

// Scratch (device globals — no allocation allowed)
__device__ __align__(16) float g_Q [MROWS * ND];
__device__ __align__(16) float g_K [MROWS * ND];
__device__ __align__(16) float g_V [MROWS * ND];   // holds V^T: [B*512+col][2048]
__device__ __align__(16) __nv_bfloat16 g_Xh[3 * (size_t)MROWS * ND];
__device__ __align__(16) __nv_bfloat16 g_Xl[3 * (size_t)MROWS * ND];
__device__ __align__(16) __nv_bfloat16 g_ATTh[(size_t)MROWS * ND];
__device__ __align__(16) __nv_bfloat16 g_ATTl[(size_t)MROWS * ND];
__device__ __align__(16) __nv_bfloat16 g_WTh[4 * (size_t)KD * ND];  // W^T [n][k] hi
__device__ __align__(16) __nv_bfloat16 g_WTl[4 * (size_t)KD * ND];  // W^T [n][k] lo

// ---------------------------------------------------------------------------
// helpers
// ---------------------------------------------------------------------------
__device__ __forceinline__ uint32_t smem_u32(const void* p) {
    uint32_t a;
    asm("{ .reg .u64 t; cvta.to.shared.u64 t, %1; cvt.u32.u64 %0, t; }"
        : "=r"(a) : "l"(p));
    return a;
}

__device__ __forceinline__ void cp16(uint32_t dst, const void* src) {
    asm volatile("cp.async.cg.shared.global [%0], [%1], 16;"
                 :: "r"(dst), "l"(src) : "memory");
}
#define CP_COMMIT() asm volatile("cp.async.commit_group;" ::: "memory")
#define CP_WAIT0()  asm volatile("cp.async.wait_group 0;" ::: "memory")
#define CP_WAIT1()  asm volatile("cp.async.wait_group 1;" ::: "memory")

__device__ __forceinline__ float to_tf32(float x) {
    float y;
    asm("cvt.rna.tf32.f32 %0, %1;" : "=f"(y) : "f"(x));
    return y;
}

__device__ __forceinline__ void mma_bf16(float* c, const uint32_t* a, const uint32_t* b) {
    asm volatile(
        "mma.sync.aligned.m16n8k16.row.col.f32.bf16.bf16.f32 "
        "{%0,%1,%2,%3}, {%4,%5,%6,%7}, {%8,%9}, {%0,%1,%2,%3};"
        : "+f"(c[0]), "+f"(c[1]), "+f"(c[2]), "+f"(c[3])
        : "r"(a[0]), "r"(a[1]), "r"(a[2]), "r"(a[3]), "r"(b[0]), "r"(b[1]));
}

__device__ __forceinline__ void mma_tf32(float* c, const uint32_t* a, const uint32_t* b) {
    asm volatile(
        "mma.sync.aligned.m16n8k8.row.col.f32.tf32.tf32.f32 "
        "{%0,%1,%2,%3}, {%4,%5,%6,%7}, {%8,%9}, {%0,%1,%2,%3};"
        : "+f"(c[0]), "+f"(c[1]), "+f"(c[2]), "+f"(c[3])
        : "r"(a[0]), "r"(a[1]), "r"(a[2]), "r"(a[3]), "r"(b[0]), "r"(b[1]));
}

__device__ __forceinline__ uint32_t pack2(__nv_bfloat16 a, __nv_bfloat16 b) {
    return (uint32_t)__bfloat16_as_ushort(a) | ((uint32_t)__bfloat16_as_ushort(b) << 16);
}

__device__ __forceinline__ void split2(float x, float y, uint32_t& hi, uint32_t& lo) {
    __nv_bfloat16 h0 = __float2bfloat16(x), h1 = __float2bfloat16(y);
    hi = pack2(h0, h1);
    lo = pack2(__float2bfloat16(x - __bfloat162float(h0)),
               __float2bfloat16(y - __bfloat162float(h1)));
}

// ---------------------------------------------------------------------------
// prep_w: W[k][n] -> W^T [n][k] bf16 hi/lo (Wq scaled by 1/8)
// ---------------------------------------------------------------------------
__global__ __launch_bounds__(256)
void prep_w(const float* __restrict__ Wq, const float* __restrict__ Wk,
            const float* __restrict__ Wv, const float* __restrict__ Wo)
{
    __shared__ float tbuf[32][33];
    const int z = blockIdx.z;
    const float* W = (z == 0) ? Wq : (z == 1) ? Wk : (z == 2) ? Wv : Wo;
    const float scale = (z == 0) ? 0.125f : 1.0f;
    __nv_bfloat16* oh = g_WTh + (size_t)z * KD * ND;
    __nv_bfloat16* ol = g_WTl + (size_t)z * KD * ND;
    const int k0 = blockIdx.x * 32, n0 = blockIdx.y * 32;
    const int lane = threadIdx.x & 31, r = threadIdx.x >> 5;

#pragma unroll
    for (int i = 0; i < 4; i++) {
        const int row = r + i * 8;
        tbuf[row][lane] = W[(size_t)(k0 + row) * ND + n0 + lane];
    }
    __syncthreads();
#pragma unroll
    for (int i = 0; i < 4; i++) {
        const int row = r + i * 8;
        const float x = tbuf[lane][row] * scale;
        const __nv_bfloat16 hb = __float2bfloat16(x);
        oh[(size_t)(n0 + row) * KD + k0 + lane] = hb;
        ol[(size_t)(n0 + row) * KD + k0 + lane] =
            __float2bfloat16(x - __bfloat162float(hb));
    }
}

// ---------------------------------------------------------------------------
// prep_x: split x (fp32) -> bf16 hi/lo, same [m][k] layout. grid (2048, 3).
// ---------------------------------------------------------------------------
__global__ __launch_bounds__(256)
void prep_x(const float* __restrict__ x1, const float* __restrict__ x2,
            const float* __restrict__ x3)
{
    const int z = blockIdx.y;
    const float* x = (z == 0) ? x1 : (z == 1) ? x2 : x3;
    __nv_bfloat16* oh = g_Xh + (size_t)z * MROWS * ND;
    __nv_bfloat16* ol = g_Xl + (size_t)z * MROWS * ND;
    const size_t idx = ((size_t)blockIdx.x * 256 + threadIdx.x) * 8;
    float4 v0 = *(const float4*)&x[idx];
    float4 v1 = *(const float4*)&x[idx + 4];
    uint32_t h[4], l[4];
    split2(v0.x, v0.y, h[0], l[0]);
    split2(v0.z, v0.w, h[1], l[1]);
    split2(v1.x, v1.y, h[2], l[2]);
    split2(v1.z, v1.w, h[3], l[3]);
    *(uint4*)&oh[idx] = make_uint4(h[0], h[1], h[2], h[3]);
    *(uint4*)&ol[idx] = make_uint4(l[0], l[1], l[2], l[3]);
}

// ---------------------------------------------------------------------------
// bf16x3 GEMM, all operands pre-split bf16, cp.async double-buffered.
// ---------------------------------------------------------------------------
#define GP 40                  // bf16 pitch
#define G_ARR 10240            // 128*80 bytes per array per buffer
#define G_BUF 40960            // 4 arrays
#define G_TOTAL 81920          // 80 KB -> 2 CTAs/SM

template <bool ROUND_TF32, bool HAS_BIAS>
__device__ __forceinline__
void gemm_body(const __nv_bfloat16* __restrict__ Ah, const __nv_bfloat16* __restrict__ Al,
               const __nv_bfloat16* __restrict__ Bh, const __nv_bfloat16* __restrict__ Bl,
               const float* __restrict__ bias, float* __restrict__ C,
               int m0, int n0, char* smc, bool write_vt)
{
    const uint32_t sb = smem_u32(smc);
    const int tid = threadIdx.x;
    const int lane = tid & 31;
    const int w = tid >> 5;
    const int wm = w & 1, wn = w >> 1;
    const int r = lane >> 2, cq = lane & 3;

    float c[4][4][4];
#pragma unroll
    for (int i = 0; i < 4; i++)
#pragma unroll
        for (int j = 0; j < 4; j++)
#pragma unroll
            for (int x = 0; x < 4; x++) c[i][j][x] = 0.f;

    auto issue = [&](int kt, int buf) {
        const int k0 = kt * 32;
        const uint32_t base = sb + (buf ? G_BUF : 0);
#pragma unroll
        for (int it = 0; it < 2; it++) {
            const int ch = tid + it * 256;
            const int row = ch >> 2, seg = ch & 3;
            const uint32_t off = row * 80 + seg * 16;
            const size_t ga = (size_t)(m0 + row) * KD + k0 + seg * 8;
            const size_t gb = (size_t)(n0 + row) * KD + k0 + seg * 8;
            cp16(base + off,             Ah + ga);
            cp16(base + G_ARR + off,     Al + ga);
            cp16(base + 2 * G_ARR + off, Bh + gb);
            cp16(base + 3 * G_ARR + off, Bl + gb);
        }
        CP_COMMIT();
    };

    issue(0, 0);

    for (int kt = 0; kt < 16; kt++) {
        if (kt < 15) { issue(kt + 1, (kt + 1) & 1); CP_WAIT1(); }
        else         { CP_WAIT0(); }
        __syncthreads();

        const char* bufp = smc + ((kt & 1) ? G_BUF : 0);
        const __nv_bfloat16* Ahs = (const __nv_bfloat16*)(bufp);
        const __nv_bfloat16* Als = (const __nv_bfloat16*)(bufp + G_ARR);
        const __nv_bfloat16* Bhs = (const __nv_bfloat16*)(bufp + 2 * G_ARR);
        const __nv_bfloat16* Bls = (const __nv_bfloat16*)(bufp + 3 * G_ARR);

#pragma unroll
        for (int ks = 0; ks < 2; ks++) {
            const int kb = ks * 16 + 2 * cq;
            uint32_t ah[4][4], al[4][4];
#pragma unroll
            for (int i = 0; i < 4; i++) {
                const int row = wm * 64 + i * 16 + r;
                ah[i][0] = *(const uint32_t*)&Ahs[row * GP + kb];
                ah[i][1] = *(const uint32_t*)&Ahs[(row + 8) * GP + kb];
                ah[i][2] = *(const uint32_t*)&Ahs[row * GP + kb + 8];
                ah[i][3] = *(const uint32_t*)&Ahs[(row + 8) * GP + kb + 8];
                al[i][0] = *(const uint32_t*)&Als[row * GP + kb];
                al[i][1] = *(const uint32_t*)&Als[(row + 8) * GP + kb];
                al[i][2] = *(const uint32_t*)&Als[row * GP + kb + 8];
                al[i][3] = *(const uint32_t*)&Als[(row + 8) * GP + kb + 8];
            }
#pragma unroll
            for (int j = 0; j < 4; j++) {
                const int n = wn * 32 + j * 8 + r;
                uint32_t bh2[2] = { *(const uint32_t*)&Bhs[n * GP + kb],
                                    *(const uint32_t*)&Bhs[n * GP + kb + 8] };
                uint32_t bl2[2] = { *(const uint32_t*)&Bls[n * GP + kb],
                                    *(const uint32_t*)&Bls[n * GP + kb + 8] };
#pragma unroll
                for (int i = 0; i < 4; i++) {
                    mma_bf16(c[i][j], ah[i], bh2);
                    mma_bf16(c[i][j], ah[i], bl2);
                    mma_bf16(c[i][j], al[i], bh2);
                }
            }
        }
        __syncthreads();
    }

#pragma unroll
    for (int i = 0; i < 4; i++) {
        const int row = m0 + wm * 64 + i * 16 + r;
#pragma unroll
        for (int j = 0; j < 4; j++) {
            const int col = n0 + wn * 32 + j * 8 + 2 * cq;
            float2 v0 = make_float2(c[i][j][0], c[i][j][1]);
            float2 v1 = make_float2(c[i][j][2], c[i][j][3]);
            if (HAS_BIAS) {
                const float2 bz = *(const float2*)&bias[col];
                v0.x += bz.x; v0.y += bz.y;
                v1.x += bz.x; v1.y += bz.y;
            }
            if (ROUND_TF32) {
                v0.x = to_tf32(v0.x); v0.y = to_tf32(v0.y);
                v1.x = to_tf32(v1.x); v1.y = to_tf32(v1.y);
            }
            if (write_vt) {
                const size_t b0 = ((size_t)(row >> 11) * 512 + col) * 2048;
                const int sq0 = row & 2047;
                C[b0 + sq0]            = v0.x;
                C[b0 + 2048 + sq0]     = v0.y;
                C[b0 + sq0 + 8]        = v1.x;
                C[b0 + 2048 + sq0 + 8] = v1.y;
            } else {
                *(float2*)&C[(size_t)row * ND + col] = v0;
                *(float2*)&C[(size_t)(row + 8) * ND + col] = v1;
            }
        }
    }
}

__global__ __launch_bounds__(256, 2)
void qkv_mma()
{
    extern __shared__ char smc[];
    const int z = blockIdx.z;
    const __nv_bfloat16* Ah = g_Xh + (size_t)z * MROWS * ND;
    const __nv_bfloat16* Al = g_Xl + (size_t)z * MROWS * ND;
    const __nv_bfloat16* Bh = g_WTh + (size_t)z * KD * ND;
    const __nv_bfloat16* Bl = g_WTl + (size_t)z * KD * ND;
    float* C = (z == 0) ? g_Q : (z == 1) ? g_K : g_V;
    gemm_body<true, false>(Ah, Al, Bh, Bl, nullptr, C,
                           blockIdx.y * 128, blockIdx.x * 128, smc, z == 2);
}

__global__ __launch_bounds__(256, 2)
void out_mma(const float* __restrict__ bias, float* __restrict__ C)
{
    extern __shared__ char smc[];
    gemm_body<false, true>(g_ATTh, g_ATTl,
                           g_WTh + (size_t)3 * KD * ND, g_WTl + (size_t)3 * KD * ND,
                           bias, C, blockIdx.y * 128, blockIdx.x * 128, smc, false);
}

// ---------------------------------------------------------------------------
// Flash attention — 128 threads / 64 queries per CTA, 4 CTAs/SM.
// Same per-warp math as R11 (bit-identical); more independent barrier
// domains per SM keeps the tensor pipe fed through exp/staging phases.
// K [key][dim] pitch 72; V^T [dim][key] pitch 72; P stays in registers.
// ---------------------------------------------------------------------------
#define AQ_PITCH 68
#define AK_PITCH 72
#define AVT_PITCH 72
#define A_QS 0
#define A_KS 4352                     // 64*68
#define A_VS (4352 + 4608)            // + 64*72
#define A_TOT_FLOATS (A_VS + 4608)    // = 13568 floats = 54272 B -> 4 CTAs/SM

__global__ __launch_bounds__(128, 4)
void attn_mma(const float* __restrict__ Q, const float* __restrict__ K,
              const float* __restrict__ VT)
{
    extern __shared__ float sm[];
    const uint32_t sb = smem_u32(sm);
    float* Qs = sm + A_QS;
    float* Ks = sm + A_KS;
    float* Vt = sm + A_VS;

    const int tid = threadIdx.x;
    const int lane = tid & 31;
    const int wq = tid >> 5;          // 0..3, warp -> 16 query rows
    const int r = lane >> 2, cq = lane & 3;

    const int bh = blockIdx.y;
    const int b = bh >> 3, h = bh & 7;
    const int q0 = blockIdx.x * 64;

    const float* Qb = Q + (size_t)(b * S1C + q0) * ND + h * 64;
    const float* Kb = K + (size_t)(b * S2C) * ND + h * 64;
    const float* VbT = VT + ((size_t)b * 512 + h * 64) * 2048;   // [64 dims][2048 seq]

    auto issueK = [&](int kt) {
#pragma unroll
        for (int it = 0; it < 8; it++) {
            const int ch = tid + it * 128;               // 0..1023
            const int row = ch >> 4, seg = ch & 15;      // key row, 16B seg
            cp16(sb + A_KS * 4 + row * (AK_PITCH * 4) + seg * 16,
                 Kb + (size_t)(kt * 64 + row) * ND + seg * 4);
        }
        CP_COMMIT();
    };
    auto issueV = [&](int kt) {
#pragma unroll
        for (int it = 0; it < 8; it++) {
            const int ch = tid + it * 128;
            const int row = ch >> 4, seg = ch & 15;      // dim row, 16B seg over keys
            cp16(sb + A_VS * 4 + row * (AVT_PITCH * 4) + seg * 16,
                 VbT + (size_t)row * 2048 + kt * 64 + seg * 4);
        }
        CP_COMMIT();
    };

    // stage Q (64 rows; already scaled + tf32-rounded)
#pragma unroll
    for (int it = 0; it < 8; it++) {
        const int ch = tid + it * 128;                   // 0..1023
        const int row = ch >> 4, seg = ch & 15;
        cp16(sb + A_QS * 4 + row * (AQ_PITCH * 4) + seg * 16,
             Qb + (size_t)row * ND + seg * 4);
    }
    CP_COMMIT();
    issueK(0);

    CP_WAIT0();
    __syncthreads();
    const int prow0 = wq * 16 + r;
    uint32_t qa[8][4];
#pragma unroll
    for (int kf = 0; kf < 8; kf++) {
        const int col = kf * 8 + 2 * cq;
        float2 lo = *(const float2*)&Qs[prow0 * AQ_PITCH + col];
        float2 hi = *(const float2*)&Qs[(prow0 + 8) * AQ_PITCH + col];
        qa[kf][0] = __float_as_uint(lo.x);
        qa[kf][1] = __float_as_uint(hi.x);
        qa[kf][2] = __float_as_uint(lo.y);
        qa[kf][3] = __float_as_uint(hi.y);
    }

    float o[8][4];
#pragma unroll
    for (int j = 0; j < 8; j++)
#pragma unroll
        for (int x = 0; x < 4; x++) o[j][x] = 0.f;
    float sum0 = 0.f, sum1 = 0.f;

    for (int kt = 0; kt < S2C / 64; kt++) {
        CP_WAIT0();
        __syncthreads();

        issueV(kt);          // overlaps QK(t)

        float s8[8][4];
#pragma unroll
        for (int j = 0; j < 8; j++)
#pragma unroll
            for (int x = 0; x < 4; x++) s8[j][x] = 0.f;

#pragma unroll
        for (int kf = 0; kf < 8; kf++) {
            const int col = kf * 8 + 2 * cq;
#pragma unroll
            for (int j = 0; j < 8; j++) {
                float2 kv = *(const float2*)&Ks[(j * 8 + r) * AK_PITCH + col];
                uint32_t kb2[2] = { __float_as_uint(kv.x),
                                    __float_as_uint(kv.y) };
                mma_tf32(s8[j], qa[kf], kb2);
            }
        }

#pragma unroll
        for (int j = 0; j < 8; j++) {
            s8[j][0] = __expf(s8[j][0]);
            s8[j][1] = __expf(s8[j][1]);
            s8[j][2] = __expf(s8[j][2]);
            s8[j][3] = __expf(s8[j][3]);
            sum0 += s8[j][0] + s8[j][1];
            sum1 += s8[j][2] + s8[j][3];
        }

        CP_WAIT0();          // V(t) complete
        __syncthreads();

        if (kt < S2C / 64 - 1) issueK(kt + 1);   // overlaps PV(t)

        // O += P @ V : P from S accumulator; V fragment = one LDS.64
#pragma unroll
        for (int jk = 0; jk < 8; jk++) {
            uint32_t pa[4];
            pa[0] = __float_as_uint(to_tf32(s8[jk][0]));
            pa[1] = __float_as_uint(to_tf32(s8[jk][2]));
            pa[2] = __float_as_uint(to_tf32(s8[jk][1]));
            pa[3] = __float_as_uint(to_tf32(s8[jk][3]));
#pragma unroll
            for (int jd = 0; jd < 8; jd++) {
                float2 vv = *(const float2*)&Vt[(jd * 8 + r) * AVT_PITCH + jk * 8 + 2 * cq];
                uint32_t vb2[2] = { __float_as_uint(vv.x),
                                    __float_as_uint(vv.y) };
                mma_tf32(o[jd], pa, vb2);
            }
        }
    }

    sum0 += __shfl_xor_sync(0xffffffffu, sum0, 1);
    sum0 += __shfl_xor_sync(0xffffffffu, sum0, 2);
    sum1 += __shfl_xor_sync(0xffffffffu, sum1, 1);
    sum1 += __shfl_xor_sync(0xffffffffu, sum1, 2);
    const float rl0 = 1.0f / sum0, rl1 = 1.0f / sum1;

    // write output as bf16 hi/lo (feeds out_mma directly)
    const int grow = b * S1C + q0 + wq * 16 + r;
#pragma unroll
    for (int j = 0; j < 8; j++) {
        const int col = h * 64 + j * 8 + 2 * cq;
        uint32_t h0, l0, h1, l1;
        split2(o[j][0] * rl0, o[j][1] * rl0, h0, l0);
        split2(o[j][2] * rl1, o[j][3] * rl1, h1, l1);
        *(uint32_t*)&g_ATTh[(size_t)grow * ND + col] = h0;
        *(uint32_t*)&g_ATTl[(size_t)grow * ND + col] = l0;
        *(uint32_t*)&g_ATTh[(size_t)(grow + 8) * ND + col] = h1;
        *(uint32_t*)&g_ATTl[(size_t)(grow + 8) * ND + col] = l1;
    }
}

// ---------------------------------------------------------------------------
// Launch
// ---------------------------------------------------------------------------
extern "C" void kernel_launch(void* const* d_in, const int* in_sizes, int n_in,
                              void* d_out, int out_size)
{
    (void)in_sizes; (void)n_in; (void)out_size;
    const float* x1 = (const float*)d_in[0];
    const float* x2 = (const float*)d_in[1];
    const float* x3 = (const float*)d_in[2];
    const float* Wq = (const float*)d_in[3];
    const float* Wk = (const float*)d_in[4];
    const float* Wv = (const float*)d_in[5];
    const float* Wo = (const float*)d_in[6];
    const float* bo = (const float*)d_in[7];
    float* out = (float*)d_out;

    float *Q, *K, *V;
    cudaGetSymbolAddress((void**)&Q, g_Q);
    cudaGetSymbolAddress((void**)&K, g_K);
    cudaGetSymbolAddress((void**)&V, g_V);

    cudaFuncSetAttribute(qkv_mma, cudaFuncAttributeMaxDynamicSharedMemorySize,
                         G_TOTAL);
    cudaFuncSetAttribute(out_mma, cudaFuncAttributeMaxDynamicSharedMemorySize,
                         G_TOTAL);
    cudaFuncSetAttribute(attn_mma, cudaFuncAttributeMaxDynamicSharedMemorySize,
                         A_TOT_FLOATS * 4);

    prep_w<<<dim3(16, 16, 4), 256>>>(Wq, Wk, Wv, Wo);
    prep_x<<<dim3(MROWS * ND / 2048, 3), 256>>>(x1, x2, x3);

    dim3 gQKV(ND / 128, MROWS / 128, 3);   // (4, 64, 3)
    qkv_mma<<<gQKV, 256, G_TOTAL>>>();

    dim3 gA(S1C / 64, BB * NH);            // (32, 32) — 64-query CTAs
    attn_mma<<<gA, 128, A_TOT_FLOATS * 4>>>(Q, K, V);

    dim3 gO(ND / 128, MROWS / 128);        // (4, 64)
    out_mma<<<gO, 256, G_TOTAL>>>(bo, out);
}

// round 13
// speedup vs baseline: 4.0425x; 1.0035x over previous
#include <cuda_runtime.h>
#include <cuda_bf16.h>
#include <cstdint>

// Problem constants
#define BB 4
#define S1C 2048
#define S2C 2048
#define NH 8
#define MROWS (BB * S1C)    // 8192
#define ND 512
#define KD 512

// Scratch (device globals — no allocation allowed)
__device__ __align__(16) float g_Q [MROWS * ND];
__device__ __align__(16) float g_K [MROWS * ND];
__device__ __align__(16) float g_V [MROWS * ND];   // holds V^T: [B*512+col][2048]
__device__ __align__(16) __nv_bfloat16 g_Xh[3 * (size_t)MROWS * ND];
__device__ __align__(16) __nv_bfloat16 g_Xl[3 * (size_t)MROWS * ND];
__device__ __align__(16) __nv_bfloat16 g_ATTh[(size_t)MROWS * ND];
__device__ __align__(16) __nv_bfloat16 g_ATTl[(size_t)MROWS * ND];
__device__ __align__(16) __nv_bfloat16 g_WTh[4 * (size_t)KD * ND];  // W^T [n][k] hi
__device__ __align__(16) __nv_bfloat16 g_WTl[4 * (size_t)KD * ND];  // W^T [n][k] lo

// ---------------------------------------------------------------------------
// helpers
// ---------------------------------------------------------------------------
__device__ __forceinline__ uint32_t smem_u32(const void* p) {
    uint32_t a;
    asm("{ .reg .u64 t; cvta.to.shared.u64 t, %1; cvt.u32.u64 %0, t; }"
        : "=r"(a) : "l"(p));
    return a;
}

__device__ __forceinline__ void cp16(uint32_t dst, const void* src) {
    asm volatile("cp.async.cg.shared.global [%0], [%1], 16;"
                 :: "r"(dst), "l"(src) : "memory");
}
#define CP_COMMIT() asm volatile("cp.async.commit_group;" ::: "memory")
#define CP_WAIT0()  asm volatile("cp.async.wait_group 0;" ::: "memory")
#define CP_WAIT1()  asm volatile("cp.async.wait_group 1;" ::: "memory")

__device__ __forceinline__ float to_tf32(float x) {
    float y;
    asm("cvt.rna.tf32.f32 %0, %1;" : "=f"(y) : "f"(x));
    return y;
}

__device__ __forceinline__ void mma_bf16(float* c, const uint32_t* a, const uint32_t* b) {
    asm volatile(
        "mma.sync.aligned.m16n8k16.row.col.f32.bf16.bf16.f32 "
        "{%0,%1,%2,%3}, {%4,%5,%6,%7}, {%8,%9}, {%0,%1,%2,%3};"
        : "+f"(c[0]), "+f"(c[1]), "+f"(c[2]), "+f"(c[3])
        : "r"(a[0]), "r"(a[1]), "r"(a[2]), "r"(a[3]), "r"(b[0]), "r"(b[1]));
}

__device__ __forceinline__ void mma_tf32(float* c, const uint32_t* a, const uint32_t* b) {
    asm volatile(
        "mma.sync.aligned.m16n8k8.row.col.f32.tf32.tf32.f32 "
        "{%0,%1,%2,%3}, {%4,%5,%6,%7}, {%8,%9}, {%0,%1,%2,%3};"
        : "+f"(c[0]), "+f"(c[1]), "+f"(c[2]), "+f"(c[3])
        : "r"(a[0]), "r"(a[1]), "r"(a[2]), "r"(a[3]), "r"(b[0]), "r"(b[1]));
}

__device__ __forceinline__ uint32_t pack2(__nv_bfloat16 a, __nv_bfloat16 b) {
    return (uint32_t)__bfloat16_as_ushort(a) | ((uint32_t)__bfloat16_as_ushort(b) << 16);
}

__device__ __forceinline__ void split2(float x, float y, uint32_t& hi, uint32_t& lo) {
    __nv_bfloat16 h0 = __float2bfloat16(x), h1 = __float2bfloat16(y);
    hi = pack2(h0, h1);
    lo = pack2(__float2bfloat16(x - __bfloat162float(h0)),
               __float2bfloat16(y - __bfloat162float(h1)));
}

// ---------------------------------------------------------------------------
// prep_w: W[k][n] -> W^T [n][k-permuted] bf16 hi/lo (Wq scaled by 1/8).
// k-permutation within each 16-block: pair order [0,4,1,5,2,6,3,7].
// stored(k) = (k&~15) + 4*((k>>1)&3) + 2*((k>>3)&1) + (k&1)
// ---------------------------------------------------------------------------
__global__ __launch_bounds__(256)
void prep_w(const float* __restrict__ Wq, const float* __restrict__ Wk,
            const float* __restrict__ Wv, const float* __restrict__ Wo)
{
    __shared__ float tbuf[32][33];
    const int z = blockIdx.z;
    const float* W = (z == 0) ? Wq : (z == 1) ? Wk : (z == 2) ? Wv : Wo;
    const float scale = (z == 0) ? 0.125f : 1.0f;
    __nv_bfloat16* oh = g_WTh + (size_t)z * KD * ND;
    __nv_bfloat16* ol = g_WTl + (size_t)z * KD * ND;
    const int k0 = blockIdx.x * 32, n0 = blockIdx.y * 32;
    const int lane = threadIdx.x & 31, r = threadIdx.x >> 5;

#pragma unroll
    for (int i = 0; i < 4; i++) {
        const int row = r + i * 8;
        tbuf[row][lane] = W[(size_t)(k0 + row) * ND + n0 + lane];
    }
    __syncthreads();
    // permuted k position for this lane
    const int kst = k0 + (lane & 16) + 4 * ((lane >> 1) & 3)
                  + 2 * ((lane >> 3) & 1) + (lane & 1);
#pragma unroll
    for (int i = 0; i < 4; i++) {
        const int row = r + i * 8;
        const float x = tbuf[lane][row] * scale;
        const __nv_bfloat16 hb = __float2bfloat16(x);
        oh[(size_t)(n0 + row) * KD + kst] = hb;
        ol[(size_t)(n0 + row) * KD + kst] =
            __float2bfloat16(x - __bfloat162float(hb));
    }
}

// ---------------------------------------------------------------------------
// prep_x: split x (fp32) -> bf16 hi/lo with k-pair permutation.
// One 16-block per thread. grid (1024, 3).
// ---------------------------------------------------------------------------
__global__ __launch_bounds__(256)
void prep_x(const float* __restrict__ x1, const float* __restrict__ x2,
            const float* __restrict__ x3)
{
    const int z = blockIdx.y;
    const float* x = (z == 0) ? x1 : (z == 1) ? x2 : x3;
    __nv_bfloat16* oh = g_Xh + (size_t)z * MROWS * ND;
    __nv_bfloat16* ol = g_Xl + (size_t)z * MROWS * ND;
    const size_t idx = ((size_t)blockIdx.x * 256 + threadIdx.x) * 16;
    float4 v0 = *(const float4*)&x[idx];
    float4 v1 = *(const float4*)&x[idx + 4];
    float4 v2 = *(const float4*)&x[idx + 8];
    float4 v3 = *(const float4*)&x[idx + 12];
    uint32_t ph[8], pl[8];
    split2(v0.x, v0.y, ph[0], pl[0]);
    split2(v0.z, v0.w, ph[1], pl[1]);
    split2(v1.x, v1.y, ph[2], pl[2]);
    split2(v1.z, v1.w, ph[3], pl[3]);
    split2(v2.x, v2.y, ph[4], pl[4]);
    split2(v2.z, v2.w, ph[5], pl[5]);
    split2(v3.x, v3.y, ph[6], pl[6]);
    split2(v3.z, v3.w, ph[7], pl[7]);
    // stored pair order: [0,4,1,5,2,6,3,7]
    *(uint4*)&oh[idx]     = make_uint4(ph[0], ph[4], ph[1], ph[5]);
    *(uint4*)&oh[idx + 8] = make_uint4(ph[2], ph[6], ph[3], ph[7]);
    *(uint4*)&ol[idx]     = make_uint4(pl[0], pl[4], pl[1], pl[5]);
    *(uint4*)&ol[idx + 8] = make_uint4(pl[2], pl[6], pl[3], pl[7]);
}

// ---------------------------------------------------------------------------
// bf16x3 GEMM, pre-split + k-pair-permuted operands, cp.async double-buffered.
// Fragments load as LDS.64 (stored cols 4cq..4cq+3 = pairs cq, cq+4).
// Pitch 48 bf16 (96B): (12*row + cq) mod 16 distinct per 16-lane phase.
// ---------------------------------------------------------------------------
#define GP 48                  // bf16 pitch
#define G_ARR 12288            // 128*96 bytes per array per buffer
#define G_BUF 49152            // 4 arrays
#define G_TOTAL 98304          // 96 KB -> 2 CTAs/SM

template <bool ROUND_TF32, bool HAS_BIAS>
__device__ __forceinline__
void gemm_body(const __nv_bfloat16* __restrict__ Ah, const __nv_bfloat16* __restrict__ Al,
               const __nv_bfloat16* __restrict__ Bh, const __nv_bfloat16* __restrict__ Bl,
               const float* __restrict__ bias, float* __restrict__ C,
               int m0, int n0, char* smc, bool write_vt)
{
    const uint32_t sb = smem_u32(smc);
    const int tid = threadIdx.x;
    const int lane = tid & 31;
    const int w = tid >> 5;
    const int wm = w & 1, wn = w >> 1;
    const int r = lane >> 2, cq = lane & 3;

    float c[4][4][4];
#pragma unroll
    for (int i = 0; i < 4; i++)
#pragma unroll
        for (int j = 0; j < 4; j++)
#pragma unroll
            for (int x = 0; x < 4; x++) c[i][j][x] = 0.f;

    auto issue = [&](int kt, int buf) {
        const int k0 = kt * 32;
        const uint32_t base = sb + (buf ? G_BUF : 0);
#pragma unroll
        for (int it = 0; it < 2; it++) {
            const int ch = tid + it * 256;
            const int row = ch >> 2, seg = ch & 3;
            const uint32_t off = row * 96 + seg * 16;
            const size_t ga = (size_t)(m0 + row) * KD + k0 + seg * 8;
            const size_t gb = (size_t)(n0 + row) * KD + k0 + seg * 8;
            cp16(base + off,             Ah + ga);
            cp16(base + G_ARR + off,     Al + ga);
            cp16(base + 2 * G_ARR + off, Bh + gb);
            cp16(base + 3 * G_ARR + off, Bl + gb);
        }
        CP_COMMIT();
    };

    issue(0, 0);

    for (int kt = 0; kt < 16; kt++) {
        if (kt < 15) { issue(kt + 1, (kt + 1) & 1); CP_WAIT1(); }
        else         { CP_WAIT0(); }
        __syncthreads();

        const char* bufp = smc + ((kt & 1) ? G_BUF : 0);
        const __nv_bfloat16* Ahs = (const __nv_bfloat16*)(bufp);
        const __nv_bfloat16* Als = (const __nv_bfloat16*)(bufp + G_ARR);
        const __nv_bfloat16* Bhs = (const __nv_bfloat16*)(bufp + 2 * G_ARR);
        const __nv_bfloat16* Bls = (const __nv_bfloat16*)(bufp + 3 * G_ARR);

#pragma unroll
        for (int ks = 0; ks < 2; ks++) {
            const int kb = ks * 16 + 4 * cq;        // stored bf16 col
            uint32_t ah[4][4], al[4][4];
#pragma unroll
            for (int i = 0; i < 4; i++) {
                const int row = wm * 64 + i * 16 + r;
                uint2 h0 = *(const uint2*)&Ahs[row * GP + kb];         // (a0,a2)
                uint2 h1 = *(const uint2*)&Ahs[(row + 8) * GP + kb];   // (a1,a3)
                ah[i][0] = h0.x; ah[i][1] = h1.x; ah[i][2] = h0.y; ah[i][3] = h1.y;
                uint2 l0 = *(const uint2*)&Als[row * GP + kb];
                uint2 l1 = *(const uint2*)&Als[(row + 8) * GP + kb];
                al[i][0] = l0.x; al[i][1] = l1.x; al[i][2] = l0.y; al[i][3] = l1.y;
            }
#pragma unroll
            for (int j = 0; j < 4; j++) {
                const int n = wn * 32 + j * 8 + r;
                uint2 bh = *(const uint2*)&Bhs[n * GP + kb];           // (b0,b1)
                uint2 bl = *(const uint2*)&Bls[n * GP + kb];
                uint32_t bh2[2] = { bh.x, bh.y };
                uint32_t bl2[2] = { bl.x, bl.y };
#pragma unroll
                for (int i = 0; i < 4; i++) {
                    mma_bf16(c[i][j], ah[i], bh2);
                    mma_bf16(c[i][j], ah[i], bl2);
                    mma_bf16(c[i][j], al[i], bh2);
                }
            }
        }
        __syncthreads();
    }

#pragma unroll
    for (int i = 0; i < 4; i++) {
        const int row = m0 + wm * 64 + i * 16 + r;
#pragma unroll
        for (int j = 0; j < 4; j++) {
            const int col = n0 + wn * 32 + j * 8 + 2 * cq;
            float2 v0 = make_float2(c[i][j][0], c[i][j][1]);
            float2 v1 = make_float2(c[i][j][2], c[i][j][3]);
            if (HAS_BIAS) {
                const float2 bz = *(const float2*)&bias[col];
                v0.x += bz.x; v0.y += bz.y;
                v1.x += bz.x; v1.y += bz.y;
            }
            if (ROUND_TF32) {
                v0.x = to_tf32(v0.x); v0.y = to_tf32(v0.y);
                v1.x = to_tf32(v1.x); v1.y = to_tf32(v1.y);
            }
            if (write_vt) {
                const size_t b0 = ((size_t)(row >> 11) * 512 + col) * 2048;
                const int sq0 = row & 2047;
                C[b0 + sq0]            = v0.x;
                C[b0 + 2048 + sq0]     = v0.y;
                C[b0 + sq0 + 8]        = v1.x;
                C[b0 + 2048 + sq0 + 8] = v1.y;
            } else {
                *(float2*)&C[(size_t)row * ND + col] = v0;
                *(float2*)&C[(size_t)(row + 8) * ND + col] = v1;
            }
        }
    }
}

__global__ __launch_bounds__(256, 2)
void qkv_mma()
{
    extern __shared__ char smc[];
    const int z = blockIdx.z;
    const __nv_bfloat16* Ah = g_Xh + (size_t)z * MROWS * ND;
    const __nv_bfloat16* Al = g_Xl + (size_t)z * MROWS * ND;
    const __nv_bfloat16* Bh = g_WTh + (size_t)z * KD * ND;
    const __nv_bfloat16* Bl = g_WTl + (size_t)z * KD * ND;
    float* C = (z == 0) ? g_Q : (z == 1) ? g_K : g_V;
    gemm_body<true, false>(Ah, Al, Bh, Bl, nullptr, C,
                           blockIdx.y * 128, blockIdx.x * 128, smc, z == 2);
}

__global__ __launch_bounds__(256, 2)
void out_mma(const float* __restrict__ bias, float* __restrict__ C)
{
    extern __shared__ char smc[];
    gemm_body<false, true>(g_ATTh, g_ATTl,
                           g_WTh + (size_t)3 * KD * ND, g_WTl + (size_t)3 * KD * ND,
                           bias, C, blockIdx.y * 128, blockIdx.x * 128, smc, false);
}

// ---------------------------------------------------------------------------
// Flash attention — 128 threads / 64 queries per CTA, 4 CTAs/SM.
// K [key][dim] pitch 72; V^T [dim][key] pitch 72; P stays in registers.
// Output written as bf16 hi/lo at k-pair-PERMUTED columns (feeds out_mma).
// ---------------------------------------------------------------------------
#define AQ_PITCH 68
#define AK_PITCH 72
#define AVT_PITCH 72
#define A_QS 0
#define A_KS 4352                     // 64*68
#define A_VS (4352 + 4608)            // + 64*72
#define A_TOT_FLOATS (A_VS + 4608)    // = 13568 floats = 54272 B -> 4 CTAs/SM

__global__ __launch_bounds__(128, 4)
void attn_mma(const float* __restrict__ Q, const float* __restrict__ K,
              const float* __restrict__ VT)
{
    extern __shared__ float sm[];
    const uint32_t sb = smem_u32(sm);
    float* Qs = sm + A_QS;
    float* Ks = sm + A_KS;
    float* Vt = sm + A_VS;

    const int tid = threadIdx.x;
    const int lane = tid & 31;
    const int wq = tid >> 5;
    const int r = lane >> 2, cq = lane & 3;

    const int bh = blockIdx.y;
    const int b = bh >> 3, h = bh & 7;
    const int q0 = blockIdx.x * 64;

    const float* Qb = Q + (size_t)(b * S1C + q0) * ND + h * 64;
    const float* Kb = K + (size_t)(b * S2C) * ND + h * 64;
    const float* VbT = VT + ((size_t)b * 512 + h * 64) * 2048;

    auto issueK = [&](int kt) {
#pragma unroll
        for (int it = 0; it < 8; it++) {
            const int ch = tid + it * 128;
            const int row = ch >> 4, seg = ch & 15;
            cp16(sb + A_KS * 4 + row * (AK_PITCH * 4) + seg * 16,
                 Kb + (size_t)(kt * 64 + row) * ND + seg * 4);
        }
        CP_COMMIT();
    };
    auto issueV = [&](int kt) {
#pragma unroll
        for (int it = 0; it < 8; it++) {
            const int ch = tid + it * 128;
            const int row = ch >> 4, seg = ch & 15;
            cp16(sb + A_VS * 4 + row * (AVT_PITCH * 4) + seg * 16,
                 VbT + (size_t)row * 2048 + kt * 64 + seg * 4);
        }
        CP_COMMIT();
    };

    // stage Q
#pragma unroll
    for (int it = 0; it < 8; it++) {
        const int ch = tid + it * 128;
        const int row = ch >> 4, seg = ch & 15;
        cp16(sb + A_QS * 4 + row * (AQ_PITCH * 4) + seg * 16,
             Qb + (size_t)row * ND + seg * 4);
    }
    CP_COMMIT();
    issueK(0);

    CP_WAIT0();
    __syncthreads();
    const int prow0 = wq * 16 + r;
    uint32_t qa[8][4];
#pragma unroll
    for (int kf = 0; kf < 8; kf++) {
        const int col = kf * 8 + 2 * cq;
        float2 lo = *(const float2*)&Qs[prow0 * AQ_PITCH + col];
        float2 hi = *(const float2*)&Qs[(prow0 + 8) * AQ_PITCH + col];
        qa[kf][0] = __float_as_uint(lo.x);
        qa[kf][1] = __float_as_uint(hi.x);
        qa[kf][2] = __float_as_uint(lo.y);
        qa[kf][3] = __float_as_uint(hi.y);
    }

    float o[8][4];
#pragma unroll
    for (int j = 0; j < 8; j++)
#pragma unroll
        for (int x = 0; x < 4; x++) o[j][x] = 0.f;
    float sum0 = 0.f, sum1 = 0.f;

    for (int kt = 0; kt < S2C / 64; kt++) {
        CP_WAIT0();
        __syncthreads();

        issueV(kt);          // overlaps QK(t)

        float s8[8][4];
#pragma unroll
        for (int j = 0; j < 8; j++)
#pragma unroll
            for (int x = 0; x < 4; x++) s8[j][x] = 0.f;

#pragma unroll
        for (int kf = 0; kf < 8; kf++) {
            const int col = kf * 8 + 2 * cq;
#pragma unroll
            for (int j = 0; j < 8; j++) {
                float2 kv = *(const float2*)&Ks[(j * 8 + r) * AK_PITCH + col];
                uint32_t kb2[2] = { __float_as_uint(kv.x),
                                    __float_as_uint(kv.y) };
                mma_tf32(s8[j], qa[kf], kb2);
            }
        }

#pragma unroll
        for (int j = 0; j < 8; j++) {
            s8[j][0] = __expf(s8[j][0]);
            s8[j][1] = __expf(s8[j][1]);
            s8[j][2] = __expf(s8[j][2]);
            s8[j][3] = __expf(s8[j][3]);
            sum0 += s8[j][0] + s8[j][1];
            sum1 += s8[j][2] + s8[j][3];
        }

        CP_WAIT0();          // V(t) complete
        __syncthreads();

        if (kt < S2C / 64 - 1) issueK(kt + 1);   // overlaps PV(t)

        // O += P @ V : P from S accumulator; V fragment = one LDS.64
#pragma unroll
        for (int jk = 0; jk < 8; jk++) {
            uint32_t pa[4];
            pa[0] = __float_as_uint(to_tf32(s8[jk][0]));
            pa[1] = __float_as_uint(to_tf32(s8[jk][2]));
            pa[2] = __float_as_uint(to_tf32(s8[jk][1]));
            pa[3] = __float_as_uint(to_tf32(s8[jk][3]));
#pragma unroll
            for (int jd = 0; jd < 8; jd++) {
                float2 vv = *(const float2*)&Vt[(jd * 8 + r) * AVT_PITCH + jk * 8 + 2 * cq];
                uint32_t vb2[2] = { __float_as_uint(vv.x),
                                    __float_as_uint(vv.y) };
                mma_tf32(o[jd], pa, vb2);
            }
        }
    }

    sum0 += __shfl_xor_sync(0xffffffffu, sum0, 1);
    sum0 += __shfl_xor_sync(0xffffffffu, sum0, 2);
    sum1 += __shfl_xor_sync(0xffffffffu, sum1, 1);
    sum1 += __shfl_xor_sync(0xffffffffu, sum1, 2);
    const float rl0 = 1.0f / sum0, rl1 = 1.0f / sum1;

    // write output as bf16 hi/lo at k-permuted columns:
    // logical col = h*64 + j*8 + 2cq -> stored = blk + 4cq + 2*(j&1)
    const int grow = b * S1C + q0 + wq * 16 + r;
#pragma unroll
    for (int j = 0; j < 8; j++) {
        const int scol = h * 64 + (j >> 1) * 16 + 4 * cq + 2 * (j & 1);
        uint32_t h0, l0, h1, l1;
        split2(o[j][0] * rl0, o[j][1] * rl0, h0, l0);
        split2(o[j][2] * rl1, o[j][3] * rl1, h1, l1);
        *(uint32_t*)&g_ATTh[(size_t)grow * ND + scol] = h0;
        *(uint32_t*)&g_ATTl[(size_t)grow * ND + scol] = l0;
        *(uint32_t*)&g_ATTh[(size_t)(grow + 8) * ND + scol] = h1;
        *(uint32_t*)&g_ATTl[(size_t)(grow + 8) * ND + scol] = l1;
    }
}

// ---------------------------------------------------------------------------
// Launch
// ---------------------------------------------------------------------------
extern "C" void kernel_launch(void* const* d_in, const int* in_sizes, int n_in,
                              void* d_out, int out_size)
{
    (void)in_sizes; (void)n_in; (void)out_size;
    const float* x1 = (const float*)d_in[0];
    const float* x2 = (const float*)d_in[1];
    const float* x3 = (const float*)d_in[2];
    const float* Wq = (const float*)d_in[3];
    const float* Wk = (const float*)d_in[4];
    const float* Wv = (const float*)d_in[5];
    const float* Wo = (const float*)d_in[6];
    const float* bo = (const float*)d_in[7];
    float* out = (float*)d_out;

    float *Q, *K, *V;
    cudaGetSymbolAddress((void**)&Q, g_Q);
    cudaGetSymbolAddress((void**)&K, g_K);
    cudaGetSymbolAddress((void**)&V, g_V);

    cudaFuncSetAttribute(qkv_mma, cudaFuncAttributeMaxDynamicSharedMemorySize,
                         G_TOTAL);
    cudaFuncSetAttribute(out_mma, cudaFuncAttributeMaxDynamicSharedMemorySize,
                         G_TOTAL);
    cudaFuncSetAttribute(attn_mma, cudaFuncAttributeMaxDynamicSharedMemorySize,
                         A_TOT_FLOATS * 4);

    prep_w<<<dim3(16, 16, 4), 256>>>(Wq, Wk, Wv, Wo);
    prep_x<<<dim3(MROWS * ND / 4096, 3), 256>>>(x1, x2, x3);

    dim3 gQKV(ND / 128, MROWS / 128, 3);   // (4, 64, 3)
    qkv_mma<<<gQKV, 256, G_TOTAL>>>();

    dim3 gA(S1C / 64, BB * NH);            // (32, 32) — 64-query CTAs
    attn_mma<<<gA, 128, A_TOT_FLOATS * 4>>>(Q, K, V);

    dim3 gO(ND / 128, MROWS / 128);        // (4, 64)
    out_mma<<<gO, 256, G_TOTAL>>>(bo, out);
}